// round 2
// baseline (speedup 1.0000x reference)
#include <cuda_runtime.h>
#include <math.h>

#define SQ   2048
#define D    1024
#define NH   16
#define DK   64
#define DFF  4096

// ---------------- scratch (no allocation allowed) ----------------
__device__ float g_norm_x[SQ * D];
__device__ float g_h[SQ * D];
__device__ float g_q[SQ * D];
__device__ float g_k[SQ * D];
__device__ float g_v[SQ * D];
__device__ float g_ctx[SQ * D];
__device__ float g_mha[SQ * D];
__device__ float g_part1[SQ * D];
__device__ float g_norm2[SQ * D];
__device__ float g_ff1[SQ * DFF];
__device__ float g_attn_scratch[(size_t)NH * SQ * SQ];  // fallback if d_out only holds `out`

// ---------------- LayerNorm: gamma*((x-mean)/(std+eps))+beta, std=sqrt(biased var) ----
__global__ __launch_bounds__(256) void ln_kernel(
    const float* __restrict__ x, const float* __restrict__ g,
    const float* __restrict__ b, float* __restrict__ out)
{
    __shared__ float red[256];
    const int row = blockIdx.x;
    const int tid = threadIdx.x;
    float4 v = *(const float4*)(x + (size_t)row * D + tid * 4);
    red[tid] = v.x + v.y + v.z + v.w;
    __syncthreads();
    for (int o = 128; o > 0; o >>= 1) { if (tid < o) red[tid] += red[tid + o]; __syncthreads(); }
    const float mean = red[0] * (1.0f / D);
    __syncthreads();
    const float dx = v.x - mean, dy = v.y - mean, dz = v.z - mean, dw = v.w - mean;
    red[tid] = dx * dx + dy * dy + dz * dz + dw * dw;
    __syncthreads();
    for (int o = 128; o > 0; o >>= 1) { if (tid < o) red[tid] += red[tid + o]; __syncthreads(); }
    const float inv = 1.0f / (sqrtf(red[0] * (1.0f / D)) + 1e-6f);
    float4 gg = *(const float4*)(g + tid * 4);
    float4 bb = *(const float4*)(b + tid * 4);
    float4 o4;
    o4.x = gg.x * dx * inv + bb.x;
    o4.y = gg.y * dy * inv + bb.y;
    o4.z = gg.z * dz * inv + bb.z;
    o4.w = gg.w * dw * inv + bb.w;
    *(float4*)(out + (size_t)row * D + tid * 4) = o4;
}

// ---------------- SGEMM: C = A[MxK] @ B[KxN] + bias (+res) (optional relu) ----------
// 128x128 block tile, BK=16, 256 threads, 8x8 per-thread micro-tile.
__global__ __launch_bounds__(256) void gemm_kernel(
    const float* __restrict__ A, const float* __restrict__ B,
    const float* __restrict__ bias, const float* __restrict__ res,
    float* __restrict__ C, int M, int N, int K, int do_relu)
{
    __shared__ float As[16][128];
    __shared__ float Bs[16][128];
    const int tid  = threadIdx.x;
    const int brow = blockIdx.y * 128;
    const int bcol = blockIdx.x * 128;
    const int trow = (tid >> 4) << 3;   // 0..120
    const int tcol = (tid & 15) << 3;   // 0..120

    float acc[8][8];
#pragma unroll
    for (int i = 0; i < 8; i++)
#pragma unroll
        for (int j = 0; j < 8; j++) acc[i][j] = 0.0f;

    const int a_r = tid >> 2;          // 0..63 (+64)
    const int a_c = (tid & 3) << 2;    // 0,4,8,12
    const int b_r = tid >> 5;          // 0..7 (+8)
    const int b_c = (tid & 31) << 2;   // 0..124

    for (int k0 = 0; k0 < K; k0 += 16) {
#pragma unroll
        for (int l = 0; l < 2; l++) {
            int r = a_r + l * 64;
            float4 va = *(const float4*)(A + (size_t)(brow + r) * K + k0 + a_c);
            As[a_c + 0][r] = va.x;
            As[a_c + 1][r] = va.y;
            As[a_c + 2][r] = va.z;
            As[a_c + 3][r] = va.w;
        }
#pragma unroll
        for (int l = 0; l < 2; l++) {
            int r = b_r + l * 8;
            *(float4*)(&Bs[r][b_c]) = *(const float4*)(B + (size_t)(k0 + r) * N + bcol + b_c);
        }
        __syncthreads();
#pragma unroll
        for (int kk = 0; kk < 16; kk++) {
            float ar[8], br[8];
#pragma unroll
            for (int i = 0; i < 8; i++) ar[i] = As[kk][trow + i];
#pragma unroll
            for (int j = 0; j < 8; j++) br[j] = Bs[kk][tcol + j];
#pragma unroll
            for (int i = 0; i < 8; i++)
#pragma unroll
                for (int j = 0; j < 8; j++)
                    acc[i][j] += ar[i] * br[j];
        }
        __syncthreads();
    }

#pragma unroll
    for (int i = 0; i < 8; i++) {
        const int row = brow + trow + i;
#pragma unroll
        for (int j = 0; j < 8; j++) {
            const int col = bcol + tcol + j;
            float v = acc[i][j] + bias[col];
            if (do_relu) v = fmaxf(v, 0.0f);
            if (res) v += res[(size_t)row * N + col];
            C[(size_t)row * N + col] = v;
        }
    }
}

// ---------------- fused causal attention: scores + softmax + attn write + PV -------
// grid = (SQ, NH); one block per (query row i, head h)
__global__ __launch_bounds__(256) void attn_kernel(
    const float* __restrict__ q, const float* __restrict__ k,
    const float* __restrict__ v, float* __restrict__ attn,
    float* __restrict__ ctx)
{
    __shared__ float qs[DK];
    __shared__ float p[SQ];
    __shared__ float red[256];
    const int i    = blockIdx.x;
    const int h    = blockIdx.y;
    const int tid  = threadIdx.x;
    const int lane = tid & 31;
    const int warp = tid >> 5;

    if (tid < DK) qs[tid] = q[(size_t)i * D + h * DK + tid];
    __syncthreads();

    // scores: one warp per key row j (coalesced 256B K reads, L2-resident)
    const float scale = 0.125f;  // 1/sqrt(64)
    for (int j = warp; j < SQ; j += 8) {
        float d = 0.0f;
        if (j <= i) {
            float2 kv = *(const float2*)(k + (size_t)j * D + h * DK + lane * 2);
            d = qs[lane * 2] * kv.x + qs[lane * 2 + 1] * kv.y;
#pragma unroll
            for (int o = 16; o > 0; o >>= 1) d += __shfl_down_sync(0xffffffff, d, o);
        }
        if (lane == 0) p[j] = (j <= i) ? d * scale : -INFINITY;
    }
    __syncthreads();

    // row max
    float m = -INFINITY;
    for (int j = tid; j < SQ; j += 256) m = fmaxf(m, p[j]);
    red[tid] = m;
    __syncthreads();
    for (int o = 128; o > 0; o >>= 1) { if (tid < o) red[tid] = fmaxf(red[tid], red[tid + o]); __syncthreads(); }
    const float mx = red[0];
    __syncthreads();

    // exp + sum
    float sum = 0.0f;
    for (int j = tid; j < SQ; j += 256) {
        float e = (j <= i) ? __expf(p[j] - mx) : 0.0f;
        p[j] = e;
        sum += e;
    }
    red[tid] = sum;
    __syncthreads();
    for (int o = 128; o > 0; o >>= 1) { if (tid < o) red[tid] += red[tid + o]; __syncthreads(); }
    const float inv = 1.0f / red[0];
    __syncthreads();

    // normalize, write attention weights (coalesced)
    float* arow = attn + ((size_t)h * SQ + i) * SQ;
    for (int j = tid; j < SQ; j += 256) {
        float w = p[j] * inv;
        p[j] = w;
        arow[j] = w;
    }
    __syncthreads();

    // ctx[i, h*64 + d] = sum_{j<=i} p[j] * v[j, h*64 + d]
    const int dd = tid & 63;
    const int sl = tid >> 6;
    float a = 0.0f;
    for (int j = sl; j <= i; j += 4)
        a += p[j] * v[(size_t)j * D + h * DK + dd];
    red[tid] = a;
    __syncthreads();
    if (tid < 64)
        ctx[(size_t)i * D + h * DK + tid] = red[tid] + red[tid + 64] + red[tid + 128] + red[tid + 192];
}

// ---------------- host driver ----------------
struct Scratch {
    float *nx, *hh, *q, *k, *v, *ctx, *mha, *p1, *n2, *ff1, *attn;
};

static Scratch get_scratch() {
    // resolved once per process; no runtime-API calls on subsequent launches
    static Scratch s = [] {
        Scratch t;
        void* p;
        cudaGetSymbolAddress(&p, g_norm_x);       t.nx   = (float*)p;
        cudaGetSymbolAddress(&p, g_h);            t.hh   = (float*)p;
        cudaGetSymbolAddress(&p, g_q);            t.q    = (float*)p;
        cudaGetSymbolAddress(&p, g_k);            t.k    = (float*)p;
        cudaGetSymbolAddress(&p, g_v);            t.v    = (float*)p;
        cudaGetSymbolAddress(&p, g_ctx);          t.ctx  = (float*)p;
        cudaGetSymbolAddress(&p, g_mha);          t.mha  = (float*)p;
        cudaGetSymbolAddress(&p, g_part1);        t.p1   = (float*)p;
        cudaGetSymbolAddress(&p, g_norm2);        t.n2   = (float*)p;
        cudaGetSymbolAddress(&p, g_ff1);          t.ff1  = (float*)p;
        cudaGetSymbolAddress(&p, g_attn_scratch); t.attn = (float*)p;
        return t;
    }();
    return s;
}

extern "C" void kernel_launch(void* const* d_in, const int* in_sizes, int n_in,
                              void* d_out, int out_size)
{
    const float* x     = (const float*)d_in[0];
    const float* g1    = (const float*)d_in[1];
    const float* beta1 = (const float*)d_in[2];
    const float* W_in  = (const float*)d_in[3];
    const float* b_in  = (const float*)d_in[4];
    const float* Wq    = (const float*)d_in[5];
    const float* bq    = (const float*)d_in[6];
    const float* Wk    = (const float*)d_in[7];
    const float* bk    = (const float*)d_in[8];
    const float* Wv    = (const float*)d_in[9];
    const float* bv    = (const float*)d_in[10];
    const float* Wo    = (const float*)d_in[11];
    const float* bo    = (const float*)d_in[12];
    const float* W2    = (const float*)d_in[13];
    const float* b2    = (const float*)d_in[14];
    const float* g2    = (const float*)d_in[15];
    const float* beta2 = (const float*)d_in[16];
    const float* Wf1   = (const float*)d_in[17];
    const float* bf1   = (const float*)d_in[18];
    const float* Wf2   = (const float*)d_in[19];
    const float* bf2   = (const float*)d_in[20];

    Scratch s = get_scratch();

    float* out  = (float*)d_out;
    // outputs: [out: SQ*D] ++ [attn_weights: NH*SQ*SQ] if the harness checks both
    const long long full = (long long)SQ * D + (long long)NH * SQ * SQ;
    float* attn = ((long long)out_size >= full) ? (out + (size_t)SQ * D) : s.attn;

    dim3 blk(256);
    dim3 grid_d(D / 128, SQ / 128);     // N=1024
    dim3 grid_ff(DFF / 128, SQ / 128);  // N=4096

    // 1. norm_x = LN(x)
    ln_kernel<<<SQ, blk>>>(x, g1, beta1, s.nx);
    // 2. h = norm_x @ W_in + b_in
    gemm_kernel<<<grid_d, blk>>>(s.nx, W_in, b_in, nullptr, s.hh, SQ, D, D, 0);
    // 3-5. q, k, v
    gemm_kernel<<<grid_d, blk>>>(s.hh, Wq, bq, nullptr, s.q, SQ, D, D, 0);
    gemm_kernel<<<grid_d, blk>>>(s.hh, Wk, bk, nullptr, s.k, SQ, D, D, 0);
    gemm_kernel<<<grid_d, blk>>>(s.hh, Wv, bv, nullptr, s.v, SQ, D, D, 0);
    // 6. attention (writes attn weights + ctx)
    attn_kernel<<<dim3(SQ, NH), blk>>>(s.q, s.k, s.v, attn, s.ctx);
    // 7. mha = ctx @ Wo + bo
    gemm_kernel<<<grid_d, blk>>>(s.ctx, Wo, bo, nullptr, s.mha, SQ, D, D, 0);
    // 8. part1 = x + mha @ W2 + b2
    gemm_kernel<<<grid_d, blk>>>(s.mha, W2, b2, x, s.p1, SQ, D, D, 0);
    // 9. norm2 = LN(part1)
    ln_kernel<<<SQ, blk>>>(s.p1, g2, beta2, s.n2);
    // 10. ff1 = relu(norm2 @ Wf1 + bf1)
    gemm_kernel<<<grid_ff, blk>>>(s.n2, Wf1, bf1, nullptr, s.ff1, SQ, DFF, D, 1);
    // 11. out = norm2 + ff1 @ Wf2 + bf2
    gemm_kernel<<<grid_d, blk>>>(s.ff1, Wf2, bf2, s.n2, out, SQ, D, DFF, 0);
}

// round 3
// speedup vs baseline: 1.6337x; 1.6337x over previous
#include <cuda_runtime.h>
#include <math.h>

#define SQ   2048
#define D    1024
#define NH   16
#define DK   64
#define DFF  4096

// ---------------- scratch (no allocation allowed) ----------------
__device__ float g_norm_x[SQ * D];
__device__ float g_h[SQ * D];
__device__ float g_q[SQ * D];
__device__ float g_k[SQ * D];
__device__ float g_v[SQ * D];
__device__ float g_ctx[SQ * D];
__device__ float g_mha[SQ * D];
__device__ float g_part1[SQ * D];
__device__ float g_norm2[SQ * D];
__device__ float g_ff1[SQ * DFF];
__device__ float g_attn_scratch[(size_t)NH * SQ * SQ];  // fallback if d_out only holds `out`

// ---------------- LayerNorm ----------------
__global__ __launch_bounds__(256) void ln_kernel(
    const float* __restrict__ x, const float* __restrict__ g,
    const float* __restrict__ b, float* __restrict__ out)
{
    __shared__ float red[256];
    const int row = blockIdx.x;
    const int tid = threadIdx.x;
    float4 v = *(const float4*)(x + (size_t)row * D + tid * 4);
    red[tid] = v.x + v.y + v.z + v.w;
    __syncthreads();
    for (int o = 128; o > 0; o >>= 1) { if (tid < o) red[tid] += red[tid + o]; __syncthreads(); }
    const float mean = red[0] * (1.0f / D);
    __syncthreads();
    const float dx = v.x - mean, dy = v.y - mean, dz = v.z - mean, dw = v.w - mean;
    red[tid] = dx * dx + dy * dy + dz * dz + dw * dw;
    __syncthreads();
    for (int o = 128; o > 0; o >>= 1) { if (tid < o) red[tid] += red[tid + o]; __syncthreads(); }
    const float inv = 1.0f / (sqrtf(red[0] * (1.0f / D)) + 1e-6f);
    float4 gg = *(const float4*)(g + tid * 4);
    float4 bb = *(const float4*)(b + tid * 4);
    float4 o4;
    o4.x = gg.x * dx * inv + bb.x;
    o4.y = gg.y * dy * inv + bb.y;
    o4.z = gg.z * dz * inv + bb.z;
    o4.w = gg.w * dw * inv + bb.w;
    *(float4*)(out + (size_t)row * D + tid * 4) = o4;
}

// ---------------- SGEMM: C = A[MxK] @ B[KxN] + bias (+res) (optional relu) ----------
__global__ __launch_bounds__(256) void gemm_kernel(
    const float* __restrict__ A, const float* __restrict__ B,
    const float* __restrict__ bias, const float* __restrict__ res,
    float* __restrict__ C, int M, int N, int K, int do_relu)
{
    __shared__ float As[16][128];
    __shared__ float Bs[16][128];
    const int tid  = threadIdx.x;
    const int brow = blockIdx.y * 128;
    const int bcol = blockIdx.x * 128;
    const int trow = (tid >> 4) << 3;
    const int tcol = (tid & 15) << 3;

    float acc[8][8];
#pragma unroll
    for (int i = 0; i < 8; i++)
#pragma unroll
        for (int j = 0; j < 8; j++) acc[i][j] = 0.0f;

    const int a_r = tid >> 2;
    const int a_c = (tid & 3) << 2;
    const int b_r = tid >> 5;
    const int b_c = (tid & 31) << 2;

    for (int k0 = 0; k0 < K; k0 += 16) {
#pragma unroll
        for (int l = 0; l < 2; l++) {
            int r = a_r + l * 64;
            float4 va = *(const float4*)(A + (size_t)(brow + r) * K + k0 + a_c);
            As[a_c + 0][r] = va.x;
            As[a_c + 1][r] = va.y;
            As[a_c + 2][r] = va.z;
            As[a_c + 3][r] = va.w;
        }
#pragma unroll
        for (int l = 0; l < 2; l++) {
            int r = b_r + l * 8;
            *(float4*)(&Bs[r][b_c]) = *(const float4*)(B + (size_t)(k0 + r) * N + bcol + b_c);
        }
        __syncthreads();
#pragma unroll
        for (int kk = 0; kk < 16; kk++) {
            float ar[8], br[8];
#pragma unroll
            for (int i = 0; i < 8; i++) ar[i] = As[kk][trow + i];
#pragma unroll
            for (int j = 0; j < 8; j++) br[j] = Bs[kk][tcol + j];
#pragma unroll
            for (int i = 0; i < 8; i++)
#pragma unroll
                for (int j = 0; j < 8; j++)
                    acc[i][j] += ar[i] * br[j];
        }
        __syncthreads();
    }

#pragma unroll
    for (int i = 0; i < 8; i++) {
        const int row = brow + trow + i;
#pragma unroll
        for (int j = 0; j < 8; j++) {
            const int col = bcol + tcol + j;
            float v = acc[i][j] + bias[col];
            if (do_relu) v = fmaxf(v, 0.0f);
            if (res) v += res[(size_t)row * N + col];
            C[(size_t)row * N + col] = v;
        }
    }
}

// ---------------- fused QKV projection: z selects {Wq,Wk,Wv} ----------------
__global__ __launch_bounds__(256) void qkv_kernel(
    const float* __restrict__ A,
    const float* __restrict__ Wq, const float* __restrict__ bq,
    const float* __restrict__ Wk, const float* __restrict__ bk,
    const float* __restrict__ Wv, const float* __restrict__ bv,
    float* __restrict__ Q, float* __restrict__ K, float* __restrict__ V)
{
    const float* B;
    const float* bias;
    float* C;
    if (blockIdx.z == 0)      { B = Wq; bias = bq; C = Q; }
    else if (blockIdx.z == 1) { B = Wk; bias = bk; C = K; }
    else                      { B = Wv; bias = bv; C = V; }

    __shared__ float As[16][128];
    __shared__ float Bs[16][128];
    const int tid  = threadIdx.x;
    const int brow = blockIdx.y * 128;
    const int bcol = blockIdx.x * 128;
    const int trow = (tid >> 4) << 3;
    const int tcol = (tid & 15) << 3;

    float acc[8][8];
#pragma unroll
    for (int i = 0; i < 8; i++)
#pragma unroll
        for (int j = 0; j < 8; j++) acc[i][j] = 0.0f;

    const int a_r = tid >> 2;
    const int a_c = (tid & 3) << 2;
    const int b_r = tid >> 5;
    const int b_c = (tid & 31) << 2;

    for (int k0 = 0; k0 < D; k0 += 16) {
#pragma unroll
        for (int l = 0; l < 2; l++) {
            int r = a_r + l * 64;
            float4 va = *(const float4*)(A + (size_t)(brow + r) * D + k0 + a_c);
            As[a_c + 0][r] = va.x;
            As[a_c + 1][r] = va.y;
            As[a_c + 2][r] = va.z;
            As[a_c + 3][r] = va.w;
        }
#pragma unroll
        for (int l = 0; l < 2; l++) {
            int r = b_r + l * 8;
            *(float4*)(&Bs[r][b_c]) = *(const float4*)(B + (size_t)(k0 + r) * D + bcol + b_c);
        }
        __syncthreads();
#pragma unroll
        for (int kk = 0; kk < 16; kk++) {
            float ar[8], br[8];
#pragma unroll
            for (int i = 0; i < 8; i++) ar[i] = As[kk][trow + i];
#pragma unroll
            for (int j = 0; j < 8; j++) br[j] = Bs[kk][tcol + j];
#pragma unroll
            for (int i = 0; i < 8; i++)
#pragma unroll
                for (int j = 0; j < 8; j++)
                    acc[i][j] += ar[i] * br[j];
        }
        __syncthreads();
    }

#pragma unroll
    for (int i = 0; i < 8; i++) {
        const int row = brow + trow + i;
#pragma unroll
        for (int j = 0; j < 8; j++) {
            const int col = bcol + tcol + j;
            C[(size_t)row * D + col] = acc[i][j] + bias[col];
        }
    }
}

// ---------------- score GEMM: S[h,i,j] = (q_i . k_j)/8 for j<=i ----------------
// grid (16, 16, NH); 128x128 tiles; fully-masked tiles early-return.
__global__ __launch_bounds__(256) void score_kernel(
    const float* __restrict__ q, const float* __restrict__ k,
    float* __restrict__ attn)
{
    const int brow = blockIdx.y * 128;
    const int bcol = blockIdx.x * 128;
    if (bcol >= brow + 128) return;   // fully masked tile
    const int h = blockIdx.z;
    const float* A = q + h * DK;      // row stride D
    const float* B = k + h * DK;

    __shared__ float As[16][128];
    __shared__ float Bs[16][128];
    const int tid  = threadIdx.x;
    const int trow = (tid >> 4) << 3;
    const int tcol = (tid & 15) << 3;

    float acc[8][8];
#pragma unroll
    for (int i = 0; i < 8; i++)
#pragma unroll
        for (int j = 0; j < 8; j++) acc[i][j] = 0.0f;

    const int a_r = tid >> 2;          // 0..63 (+64)
    const int a_c = (tid & 3) << 2;    // 0,4,8,12

    for (int k0 = 0; k0 < DK; k0 += 16) {
#pragma unroll
        for (int l = 0; l < 2; l++) {
            int r = a_r + l * 64;
            float4 va = *(const float4*)(A + (size_t)(brow + r) * D + k0 + a_c);
            As[a_c + 0][r] = va.x;
            As[a_c + 1][r] = va.y;
            As[a_c + 2][r] = va.z;
            As[a_c + 3][r] = va.w;
            float4 vb = *(const float4*)(B + (size_t)(bcol + r) * D + k0 + a_c);
            Bs[a_c + 0][r] = vb.x;
            Bs[a_c + 1][r] = vb.y;
            Bs[a_c + 2][r] = vb.z;
            Bs[a_c + 3][r] = vb.w;
        }
        __syncthreads();
#pragma unroll
        for (int kk = 0; kk < 16; kk++) {
            float ar[8], br[8];
#pragma unroll
            for (int i = 0; i < 8; i++) ar[i] = As[kk][trow + i];
#pragma unroll
            for (int j = 0; j < 8; j++) br[j] = Bs[kk][tcol + j];
#pragma unroll
            for (int i = 0; i < 8; i++)
#pragma unroll
                for (int j = 0; j < 8; j++)
                    acc[i][j] += ar[i] * br[j];
        }
        __syncthreads();
    }

#pragma unroll
    for (int i = 0; i < 8; i++) {
        const int row = brow + trow + i;
        float* arow = attn + ((size_t)h * SQ + row) * SQ;
#pragma unroll
        for (int j = 0; j < 8; j++) {
            const int col = bcol + tcol + j;
            if (col <= row) arow[col] = acc[i][j] * 0.125f;
        }
    }
}

// ---------------- row softmax (in-place on attn), zero-fills j>i ----------------
__global__ __launch_bounds__(256) void softmax_kernel(float* __restrict__ attn)
{
    __shared__ float p[SQ];
    __shared__ float red[256];
    const int i   = blockIdx.x;
    const int h   = blockIdx.y;
    const int tid = threadIdx.x;
    float* row = attn + ((size_t)h * SQ + i) * SQ;

    float m = -INFINITY;
    for (int j = tid; j <= i; j += 256) { float s = row[j]; p[j] = s; m = fmaxf(m, s); }
    red[tid] = m;
    __syncthreads();
    for (int o = 128; o > 0; o >>= 1) { if (tid < o) red[tid] = fmaxf(red[tid], red[tid + o]); __syncthreads(); }
    const float mx = red[0];
    __syncthreads();

    float sum = 0.0f;
    for (int j = tid; j <= i; j += 256) { float e = __expf(p[j] - mx); p[j] = e; sum += e; }
    red[tid] = sum;
    __syncthreads();
    for (int o = 128; o > 0; o >>= 1) { if (tid < o) red[tid] += red[tid + o]; __syncthreads(); }
    const float inv = 1.0f / red[0];
    __syncthreads();

    for (int j = tid; j <= i; j += 256) row[j] = p[j] * inv;
    for (int j = i + 1 + tid; j < SQ; j += 256) row[j] = 0.0f;  // exact zeros above diagonal
}

// ---------------- AV GEMM: ctx[i, h*64+d] = sum_j attn[h,i,j] * v[j, h*64+d] ------
// grid (16, NH); tile 128 rows x 64 cols; K truncated at brow+128 (rest is zero).
__global__ __launch_bounds__(256) void av_kernel(
    const float* __restrict__ attn, const float* __restrict__ v,
    float* __restrict__ ctx)
{
    const int brow = blockIdx.x * 128;
    const int h    = blockIdx.y;
    const float* A = attn + (size_t)h * SQ * SQ;  // [SQ, SQ]
    const float* B = v + h * DK;                  // row stride D

    __shared__ float As[16][128];
    __shared__ float Bs[16][64];
    const int tid  = threadIdx.x;
    const int trow = (tid >> 4) << 3;  // 0..120
    const int tcol = (tid & 15) << 2;  // 0..60

    float acc[8][4];
#pragma unroll
    for (int i = 0; i < 8; i++)
#pragma unroll
        for (int j = 0; j < 4; j++) acc[i][j] = 0.0f;

    const int a_r = tid >> 2;          // 0..63 (+64)
    const int a_c = (tid & 3) << 2;
    const int b_r = tid >> 4;          // 0..15
    const int b_c = (tid & 15) << 2;   // 0..60

    const int kmax = brow + 128;       // attn[i, j>i] == 0
    for (int k0 = 0; k0 < kmax; k0 += 16) {
#pragma unroll
        for (int l = 0; l < 2; l++) {
            int r = a_r + l * 64;
            float4 va = *(const float4*)(A + (size_t)(brow + r) * SQ + k0 + a_c);
            As[a_c + 0][r] = va.x;
            As[a_c + 1][r] = va.y;
            As[a_c + 2][r] = va.z;
            As[a_c + 3][r] = va.w;
        }
        *(float4*)(&Bs[b_r][b_c]) = *(const float4*)(B + (size_t)(k0 + b_r) * D + b_c);
        __syncthreads();
#pragma unroll
        for (int kk = 0; kk < 16; kk++) {
            float ar[8], br[4];
#pragma unroll
            for (int i = 0; i < 8; i++) ar[i] = As[kk][trow + i];
#pragma unroll
            for (int j = 0; j < 4; j++) br[j] = Bs[kk][tcol + j];
#pragma unroll
            for (int i = 0; i < 8; i++)
#pragma unroll
                for (int j = 0; j < 4; j++)
                    acc[i][j] += ar[i] * br[j];
        }
        __syncthreads();
    }

#pragma unroll
    for (int i = 0; i < 8; i++) {
        const int row = brow + trow + i;
#pragma unroll
        for (int j = 0; j < 4; j++)
            ctx[(size_t)row * D + h * DK + tcol + j] = acc[i][j];
    }
}

// ---------------- host driver ----------------
struct Scratch {
    float *nx, *hh, *q, *k, *v, *ctx, *mha, *p1, *n2, *ff1, *attn;
};

static Scratch get_scratch() {
    static Scratch s = [] {
        Scratch t;
        void* p;
        cudaGetSymbolAddress(&p, g_norm_x);       t.nx   = (float*)p;
        cudaGetSymbolAddress(&p, g_h);            t.hh   = (float*)p;
        cudaGetSymbolAddress(&p, g_q);            t.q    = (float*)p;
        cudaGetSymbolAddress(&p, g_k);            t.k    = (float*)p;
        cudaGetSymbolAddress(&p, g_v);            t.v    = (float*)p;
        cudaGetSymbolAddress(&p, g_ctx);          t.ctx  = (float*)p;
        cudaGetSymbolAddress(&p, g_mha);          t.mha  = (float*)p;
        cudaGetSymbolAddress(&p, g_part1);        t.p1   = (float*)p;
        cudaGetSymbolAddress(&p, g_norm2);        t.n2   = (float*)p;
        cudaGetSymbolAddress(&p, g_ff1);          t.ff1  = (float*)p;
        cudaGetSymbolAddress(&p, g_attn_scratch); t.attn = (float*)p;
        return t;
    }();
    return s;
}

extern "C" void kernel_launch(void* const* d_in, const int* in_sizes, int n_in,
                              void* d_out, int out_size)
{
    const float* x     = (const float*)d_in[0];
    const float* g1    = (const float*)d_in[1];
    const float* beta1 = (const float*)d_in[2];
    const float* W_in  = (const float*)d_in[3];
    const float* b_in  = (const float*)d_in[4];
    const float* Wq    = (const float*)d_in[5];
    const float* bq    = (const float*)d_in[6];
    const float* Wk    = (const float*)d_in[7];
    const float* bk    = (const float*)d_in[8];
    const float* Wv    = (const float*)d_in[9];
    const float* bv    = (const float*)d_in[10];
    const float* Wo    = (const float*)d_in[11];
    const float* bo    = (const float*)d_in[12];
    const float* W2    = (const float*)d_in[13];
    const float* b2    = (const float*)d_in[14];
    const float* g2    = (const float*)d_in[15];
    const float* beta2 = (const float*)d_in[16];
    const float* Wf1   = (const float*)d_in[17];
    const float* bf1   = (const float*)d_in[18];
    const float* Wf2   = (const float*)d_in[19];
    const float* bf2   = (const float*)d_in[20];

    Scratch s = get_scratch();

    float* out  = (float*)d_out;
    const long long full = (long long)SQ * D + (long long)NH * SQ * SQ;
    float* attn = ((long long)out_size >= full) ? (out + (size_t)SQ * D) : s.attn;

    dim3 blk(256);
    dim3 grid_d(D / 128, SQ / 128);      // 8 x 16
    dim3 grid_ff(DFF / 128, SQ / 128);   // 32 x 16
    dim3 grid_qkv(D / 128, SQ / 128, 3); // 8 x 16 x 3
    dim3 grid_sc(SQ / 128, SQ / 128, NH);
    dim3 grid_sm(SQ, NH);
    dim3 grid_av(SQ / 128, NH);

    ln_kernel<<<SQ, blk>>>(x, g1, beta1, s.nx);
    gemm_kernel<<<grid_d, blk>>>(s.nx, W_in, b_in, nullptr, s.hh, SQ, D, D, 0);
    qkv_kernel<<<grid_qkv, blk>>>(s.hh, Wq, bq, Wk, bk, Wv, bv, s.q, s.k, s.v);
    score_kernel<<<grid_sc, blk>>>(s.q, s.k, attn);
    softmax_kernel<<<grid_sm, blk>>>(attn);
    av_kernel<<<grid_av, blk>>>(attn, s.v, s.ctx);
    gemm_kernel<<<grid_d, blk>>>(s.ctx, Wo, bo, nullptr, s.mha, SQ, D, D, 0);
    gemm_kernel<<<grid_d, blk>>>(s.mha, W2, b2, x, s.p1, SQ, D, D, 0);
    ln_kernel<<<SQ, blk>>>(s.p1, g2, beta2, s.n2);
    gemm_kernel<<<grid_ff, blk>>>(s.n2, Wf1, bf1, nullptr, s.ff1, SQ, DFF, D, 1);
    gemm_kernel<<<grid_d, blk>>>(s.ff1, Wf2, bf2, s.n2, out, SQ, D, DFF, 0);
}

// round 5
// speedup vs baseline: 3.0579x; 1.8718x over previous
#include <cuda_runtime.h>
#include <cuda_bf16.h>
#include <math.h>
#include <stdint.h>

#define SQ   2048
#define D    1024
#define NH   16
#define DK   64
#define DFF  4096

// ================= PTX helpers (baseline ISA only: sm_80-level) =============
__device__ __forceinline__ uint32_t smem_u32(const void* p) {
    uint32_t a;
    asm("{ .reg .u64 t; cvta.to.shared.u64 t, %1; cvt.u32.u64 %0, t; }" : "=r"(a) : "l"(p));
    return a;
}
__device__ __forceinline__ void cpa16(uint32_t dst, const void* src) {
    asm volatile("cp.async.cg.shared.global [%0], [%1], 16;" :: "r"(dst), "l"(src));
}
#define CPA_COMMIT() asm volatile("cp.async.commit_group;" ::: "memory")
__device__ __forceinline__ void ldm_x4(uint32_t& r0, uint32_t& r1, uint32_t& r2, uint32_t& r3, uint32_t addr) {
    asm volatile("ldmatrix.sync.aligned.m8n8.x4.shared.b16 {%0,%1,%2,%3}, [%4];"
                 : "=r"(r0), "=r"(r1), "=r"(r2), "=r"(r3) : "r"(addr));
}
__device__ __forceinline__ void ldm_x2(uint32_t& r0, uint32_t& r1, uint32_t addr) {
    asm volatile("ldmatrix.sync.aligned.m8n8.x2.shared.b16 {%0,%1}, [%2];"
                 : "=r"(r0), "=r"(r1) : "r"(addr));
}
__device__ __forceinline__ void mma_bf16(float* c, uint32_t a0, uint32_t a1, uint32_t a2, uint32_t a3,
                                         uint32_t b0, uint32_t b1) {
    asm volatile("mma.sync.aligned.m16n8k16.row.col.f32.bf16.bf16.f32 "
                 "{%0,%1,%2,%3}, {%4,%5,%6,%7}, {%8,%9}, {%0,%1,%2,%3};"
                 : "+f"(c[0]), "+f"(c[1]), "+f"(c[2]), "+f"(c[3])
                 : "r"(a0), "r"(a1), "r"(a2), "r"(a3), "r"(b0), "r"(b1));
}

// ================= scratch =================
__device__ __nv_bfloat16 g_nx_h[SQ * D],  g_nx_l[SQ * D];
__device__ __nv_bfloat16 g_h_h[SQ * D],   g_h_l[SQ * D];
__device__ float         g_qkv[SQ * 3 * D];
__device__ __nv_bfloat16 g_ctx_h[SQ * D], g_ctx_l[SQ * D];
__device__ __nv_bfloat16 g_mha_h[SQ * D], g_mha_l[SQ * D];
__device__ float         g_p1[SQ * D];
__device__ float         g_n2[SQ * D];
__device__ __nv_bfloat16 g_n2_h[SQ * D],  g_n2_l[SQ * D];
__device__ __nv_bfloat16 g_ff1_h[SQ * DFF], g_ff1_l[SQ * DFF];
__device__ float         g_attn_scratch[(size_t)NH * SQ * SQ];
// transposed/split weights [N, K]
__device__ __nv_bfloat16 g_wint_h[D * D],      g_wint_l[D * D];
__device__ __nv_bfloat16 g_wqkvt_h[3 * D * D], g_wqkvt_l[3 * D * D];
__device__ __nv_bfloat16 g_wot_h[D * D],       g_wot_l[D * D];
__device__ __nv_bfloat16 g_w2t_h[D * D],       g_w2t_l[D * D];
__device__ __nv_bfloat16 g_wf1t_h[DFF * D],    g_wf1t_l[DFF * D];
__device__ __nv_bfloat16 g_wf2t_h[D * DFF],    g_wf2t_l[D * DFF];
__device__ float         g_bqkv[3 * D];

// ================= weight prep: W[K,N] fp32 -> T[N,K] bf16 hi/lo =============
__global__ __launch_bounds__(256) void wprep_kernel(
    const float* __restrict__ W, __nv_bfloat16* __restrict__ Th,
    __nv_bfloat16* __restrict__ Tl, int K, int N, int rowoff)
{
    __shared__ float t[32][33];
    const int n0 = blockIdx.x * 32, k0 = blockIdx.y * 32;
    const int tx = threadIdx.x, ty = threadIdx.y;
    for (int i = ty; i < 32; i += 8)
        t[i][tx] = W[(size_t)(k0 + i) * N + n0 + tx];
    __syncthreads();
    for (int i = ty; i < 32; i += 8) {
        float v = t[tx][i];
        __nv_bfloat16 h = __float2bfloat16_rn(v);
        size_t o = (size_t)(rowoff + n0 + i) * K + k0 + tx;
        Th[o] = h;
        Tl[o] = __float2bfloat16_rn(v - __bfloat162float(h));
    }
}

// ================= LayerNorm (optional fp32 out, optional bf16 hi/lo) ========
template<int WF32, int WSPLIT>
__global__ __launch_bounds__(256) void ln_kernel(
    const float* __restrict__ x, const float* __restrict__ g,
    const float* __restrict__ b, float* __restrict__ outf,
    __nv_bfloat16* __restrict__ oh, __nv_bfloat16* __restrict__ ol)
{
    __shared__ float red[256];
    const int row = blockIdx.x;
    const int tid = threadIdx.x;
    float4 v = *(const float4*)(x + (size_t)row * D + tid * 4);
    red[tid] = v.x + v.y + v.z + v.w;
    __syncthreads();
    for (int o = 128; o > 0; o >>= 1) { if (tid < o) red[tid] += red[tid + o]; __syncthreads(); }
    const float mean = red[0] * (1.0f / D);
    __syncthreads();
    const float dx = v.x - mean, dy = v.y - mean, dz = v.z - mean, dw = v.w - mean;
    red[tid] = dx * dx + dy * dy + dz * dz + dw * dw;
    __syncthreads();
    for (int o = 128; o > 0; o >>= 1) { if (tid < o) red[tid] += red[tid + o]; __syncthreads(); }
    const float inv = 1.0f / (sqrtf(red[0] * (1.0f / D)) + 1e-6f);
    float4 gg = *(const float4*)(g + tid * 4);
    float4 bb = *(const float4*)(b + tid * 4);
    float o0 = gg.x * dx * inv + bb.x;
    float o1 = gg.y * dy * inv + bb.y;
    float o2 = gg.z * dz * inv + bb.z;
    float o3 = gg.w * dw * inv + bb.w;
    const size_t base = (size_t)row * D + tid * 4;
    if (WF32) {
        float4 o4 = {o0, o1, o2, o3};
        *(float4*)(outf + base) = o4;
    }
    if (WSPLIT) {
        float vv[4] = {o0, o1, o2, o3};
        __nv_bfloat16 hs[4], ls[4];
#pragma unroll
        for (int i = 0; i < 4; i++) {
            hs[i] = __float2bfloat16_rn(vv[i]);
            ls[i] = __float2bfloat16_rn(vv[i] - __bfloat162float(hs[i]));
        }
        *(uint2*)(oh + base) = *(uint2*)hs;
        *(uint2*)(ol + base) = *(uint2*)ls;
    }
}

// ================= mma.sync GEMM: C[M,N] = A[M,K] @ T[N,K]^T =================
// A bf16 hi/lo [M,K]; B bf16 hi/lo [N,K] (pre-transposed).
// 128x128 CTA tile, BK=32, 8 warps (warp tile 64x32), cp.async double buffer.
// 3-product bf16 emulation: Ah*Bh + Ah*Bl + Al*Bh.
#define STG_A_H 0
#define STG_A_L 8192
#define STG_B_H 16384
#define STG_B_L 24576
#define STG_SZ  32768
#define MMA_SMEM (2 * STG_SZ)

// swizzled byte offset for (row, kb16) in a [128][32] bf16 tile (64B rows)
__device__ __forceinline__ uint32_t swz(int row, int kb) {
    return (uint32_t)(row * 64 + ((kb ^ ((row >> 1) & 3)) << 4));
}

__device__ __forceinline__ void load_tile(
    const __nv_bfloat16* __restrict__ g, int ld, int row0, int k0, uint32_t sbase, int tid)
{
#pragma unroll
    for (int it = 0; it < 2; it++) {
        int c = tid + (it << 8);   // 0..511
        int row = c >> 2, kb = c & 3;
        cpa16(sbase + swz(row, kb), g + (size_t)(row0 + row) * ld + k0 + kb * 8);
    }
}

template<int WF32, int WSPLIT, int RELU, int RESID>
__global__ __launch_bounds__(256, 1) void mma_gemm(
    const __nv_bfloat16* __restrict__ Ah, const __nv_bfloat16* __restrict__ Al,
    const __nv_bfloat16* __restrict__ Bh, const __nv_bfloat16* __restrict__ Bl,
    const float* __restrict__ bias, const float* __restrict__ res,
    float* __restrict__ Cf, __nv_bfloat16* __restrict__ Chi, __nv_bfloat16* __restrict__ Clo,
    int N, int K)
{
    extern __shared__ char smem[];
    const uint32_t sb = smem_u32(smem);
    const int tid = threadIdx.x, wid = tid >> 5, lane = tid & 31;
    const int warp_m = wid & 1;        // 2 x 64 rows
    const int warp_n = wid >> 1;       // 4 x 32 cols
    const int brow = blockIdx.y * 128, bcol = blockIdx.x * 128;

    float acc[4][4][4];
#pragma unroll
    for (int a = 0; a < 4; a++)
#pragma unroll
        for (int b = 0; b < 4; b++)
#pragma unroll
            for (int c = 0; c < 4; c++) acc[a][b][c] = 0.0f;

    // prologue: stage 0
    load_tile(Ah, K, brow, 0, sb + STG_A_H, tid);
    load_tile(Al, K, brow, 0, sb + STG_A_L, tid);
    load_tile(Bh, K, bcol, 0, sb + STG_B_H, tid);
    load_tile(Bl, K, bcol, 0, sb + STG_B_L, tid);
    CPA_COMMIT();

    // ldmatrix lane addressing (constant per thread)
    const int tileA = lane >> 3;
    const int rinA  = (lane & 7) + ((tileA & 1) << 3);   // row within 16
    const int kbA   = tileA >> 1;                        // 0/1 -> k8-halves
    const int i16   = lane & 15;
    const int rinB  = i16 & 7;
    const int kbB   = i16 >> 3;

    const int nch = K >> 5;
    for (int i = 0; i < nch; i++) {
        if (i + 1 < nch) {
            const uint32_t st = sb + ((i + 1) & 1) * STG_SZ;
            const int k0 = (i + 1) << 5;
            load_tile(Ah, K, brow, k0, st + STG_A_H, tid);
            load_tile(Al, K, brow, k0, st + STG_A_L, tid);
            load_tile(Bh, K, bcol, k0, st + STG_B_H, tid);
            load_tile(Bl, K, bcol, k0, st + STG_B_L, tid);
            CPA_COMMIT();
            asm volatile("cp.async.wait_group 1;" ::: "memory");
        } else {
            asm volatile("cp.async.wait_group 0;" ::: "memory");
        }
        __syncthreads();

        const uint32_t st = sb + (i & 1) * STG_SZ;
#pragma unroll
        for (int ks = 0; ks < 2; ks++) {
            // B fragments (persist across mt loop)
            uint32_t bh[4][2], bl[4][2];
#pragma unroll
            for (int nt = 0; nt < 4; nt++) {
                const int rowb = warp_n * 32 + nt * 8 + rinB;
                const uint32_t off = swz(rowb, (ks << 1) + kbB);
                ldm_x2(bh[nt][0], bh[nt][1], st + STG_B_H + off);
                ldm_x2(bl[nt][0], bl[nt][1], st + STG_B_L + off);
            }
#pragma unroll
            for (int mt = 0; mt < 4; mt++) {
                const int rowa = warp_m * 64 + mt * 16 + rinA;
                const uint32_t off = swz(rowa, (ks << 1) + kbA);
                uint32_t a0, a1, a2, a3, l0, l1, l2, l3;
                ldm_x4(a0, a1, a2, a3, st + STG_A_H + off);
                ldm_x4(l0, l1, l2, l3, st + STG_A_L + off);
#pragma unroll
                for (int nt = 0; nt < 4; nt++) {
                    mma_bf16(acc[mt][nt], a0, a1, a2, a3, bh[nt][0], bh[nt][1]);
                    mma_bf16(acc[mt][nt], a0, a1, a2, a3, bl[nt][0], bl[nt][1]);
                    mma_bf16(acc[mt][nt], l0, l1, l2, l3, bh[nt][0], bh[nt][1]);
                }
            }
        }
        __syncthreads();
    }

    // epilogue
    const int g4 = lane >> 2, t4 = lane & 3;
#pragma unroll
    for (int mt = 0; mt < 4; mt++) {
#pragma unroll
        for (int half = 0; half < 2; half++) {
            const int row = brow + warp_m * 64 + mt * 16 + g4 + half * 8;
#pragma unroll
            for (int nt = 0; nt < 4; nt++) {
                const int col = bcol + warp_n * 32 + nt * 8 + t4 * 2;
                float v0 = acc[mt][nt][half * 2 + 0] + bias[col];
                float v1 = acc[mt][nt][half * 2 + 1] + bias[col + 1];
                if (RELU) { v0 = fmaxf(v0, 0.0f); v1 = fmaxf(v1, 0.0f); }
                const size_t o = (size_t)row * N + col;
                if (RESID) { v0 += res[o]; v1 += res[o + 1]; }
                if (WF32) {
                    float2 f2 = {v0, v1};
                    *(float2*)(Cf + o) = f2;
                }
                if (WSPLIT) {
                    __nv_bfloat16 h0 = __float2bfloat16_rn(v0);
                    __nv_bfloat16 h1 = __float2bfloat16_rn(v1);
                    __nv_bfloat16 q0 = __float2bfloat16_rn(v0 - __bfloat162float(h0));
                    __nv_bfloat16 q1 = __float2bfloat16_rn(v1 - __bfloat162float(h1));
                    __nv_bfloat162 hp = {h0, h1}, lp = {q0, q1};
                    *(__nv_bfloat162*)(Chi + o) = hp;
                    *(__nv_bfloat162*)(Clo + o) = lp;
                }
            }
        }
    }
}

// ================= attention (CUDA-core fp32) ================================
__global__ __launch_bounds__(256) void score_kernel(
    const float* __restrict__ q, const float* __restrict__ k,
    float* __restrict__ attn, int ldq)
{
    const int brow = blockIdx.y * 128;
    const int bcol = blockIdx.x * 128;
    if (bcol >= brow + 128) return;
    const int h = blockIdx.z;
    const float* A = q + h * DK;
    const float* B = k + h * DK;

    __shared__ float As[16][128];
    __shared__ float Bs[16][128];
    const int tid  = threadIdx.x;
    const int trow = (tid >> 4) << 3;
    const int tcol = (tid & 15) << 3;

    float acc[8][8];
#pragma unroll
    for (int i = 0; i < 8; i++)
#pragma unroll
        for (int j = 0; j < 8; j++) acc[i][j] = 0.0f;

    const int a_r = tid >> 2;
    const int a_c = (tid & 3) << 2;

    for (int k0 = 0; k0 < DK; k0 += 16) {
#pragma unroll
        for (int l = 0; l < 2; l++) {
            int r = a_r + l * 64;
            float4 va = *(const float4*)(A + (size_t)(brow + r) * ldq + k0 + a_c);
            As[a_c + 0][r] = va.x;  As[a_c + 1][r] = va.y;
            As[a_c + 2][r] = va.z;  As[a_c + 3][r] = va.w;
            float4 vb = *(const float4*)(B + (size_t)(bcol + r) * ldq + k0 + a_c);
            Bs[a_c + 0][r] = vb.x;  Bs[a_c + 1][r] = vb.y;
            Bs[a_c + 2][r] = vb.z;  Bs[a_c + 3][r] = vb.w;
        }
        __syncthreads();
#pragma unroll
        for (int kk = 0; kk < 16; kk++) {
            float ar[8], br[8];
#pragma unroll
            for (int i = 0; i < 8; i++) ar[i] = As[kk][trow + i];
#pragma unroll
            for (int j = 0; j < 8; j++) br[j] = Bs[kk][tcol + j];
#pragma unroll
            for (int i = 0; i < 8; i++)
#pragma unroll
                for (int j = 0; j < 8; j++)
                    acc[i][j] += ar[i] * br[j];
        }
        __syncthreads();
    }

#pragma unroll
    for (int i = 0; i < 8; i++) {
        const int row = brow + trow + i;
        float* arow = attn + ((size_t)h * SQ + row) * SQ;
#pragma unroll
        for (int j = 0; j < 8; j++) {
            const int col = bcol + tcol + j;
            if (col <= row) arow[col] = acc[i][j] * 0.125f;
        }
    }
}

__global__ __launch_bounds__(256) void softmax_kernel(float* __restrict__ attn)
{
    __shared__ float p[SQ];
    __shared__ float red[256];
    const int i   = blockIdx.x;
    const int h   = blockIdx.y;
    const int tid = threadIdx.x;
    float* row = attn + ((size_t)h * SQ + i) * SQ;

    float m = -INFINITY;
    for (int j = tid; j <= i; j += 256) { float s = row[j]; p[j] = s; m = fmaxf(m, s); }
    red[tid] = m;
    __syncthreads();
    for (int o = 128; o > 0; o >>= 1) { if (tid < o) red[tid] = fmaxf(red[tid], red[tid + o]); __syncthreads(); }
    const float mx = red[0];
    __syncthreads();

    float sum = 0.0f;
    for (int j = tid; j <= i; j += 256) { float e = __expf(p[j] - mx); p[j] = e; sum += e; }
    red[tid] = sum;
    __syncthreads();
    for (int o = 128; o > 0; o >>= 1) { if (tid < o) red[tid] += red[tid + o]; __syncthreads(); }
    const float inv = 1.0f / red[0];
    __syncthreads();

    for (int j = tid; j <= i; j += 256) row[j] = p[j] * inv;
    for (int j = i + 1 + tid; j < SQ; j += 256) row[j] = 0.0f;
}

// AV: ctx (bf16 hi/lo) = attn @ V
__global__ __launch_bounds__(256) void av_kernel(
    const float* __restrict__ attn, const float* __restrict__ v,
    __nv_bfloat16* __restrict__ ch, __nv_bfloat16* __restrict__ cl, int ldv)
{
    const int brow = blockIdx.x * 128;
    const int h    = blockIdx.y;
    const float* A = attn + (size_t)h * SQ * SQ;
    const float* B = v + h * DK;

    __shared__ float As[16][128];
    __shared__ float Bs[16][64];
    const int tid  = threadIdx.x;
    const int trow = (tid >> 4) << 3;
    const int tcol = (tid & 15) << 2;

    float acc[8][4];
#pragma unroll
    for (int i = 0; i < 8; i++)
#pragma unroll
        for (int j = 0; j < 4; j++) acc[i][j] = 0.0f;

    const int a_r = tid >> 2;
    const int a_c = (tid & 3) << 2;
    const int b_r = tid >> 4;
    const int b_c = (tid & 15) << 2;

    const int kmax = brow + 128;
    for (int k0 = 0; k0 < kmax; k0 += 16) {
#pragma unroll
        for (int l = 0; l < 2; l++) {
            int r = a_r + l * 64;
            float4 va = *(const float4*)(A + (size_t)(brow + r) * SQ + k0 + a_c);
            As[a_c + 0][r] = va.x;  As[a_c + 1][r] = va.y;
            As[a_c + 2][r] = va.z;  As[a_c + 3][r] = va.w;
        }
        *(float4*)(&Bs[b_r][b_c]) = *(const float4*)(B + (size_t)(k0 + b_r) * ldv + b_c);
        __syncthreads();
#pragma unroll
        for (int kk = 0; kk < 16; kk++) {
            float ar[8], br[4];
#pragma unroll
            for (int i = 0; i < 8; i++) ar[i] = As[kk][trow + i];
#pragma unroll
            for (int j = 0; j < 4; j++) br[j] = Bs[kk][tcol + j];
#pragma unroll
            for (int i = 0; i < 8; i++)
#pragma unroll
                for (int j = 0; j < 4; j++)
                    acc[i][j] += ar[i] * br[j];
        }
        __syncthreads();
    }

#pragma unroll
    for (int i = 0; i < 8; i++) {
        const int row = brow + trow + i;
#pragma unroll
        for (int j = 0; j < 4; j++) {
            float vv = acc[i][j];
            __nv_bfloat16 hh = __float2bfloat16_rn(vv);
            size_t o = (size_t)row * D + h * DK + tcol + j;
            ch[o] = hh;
            cl[o] = __float2bfloat16_rn(vv - __bfloat162float(hh));
        }
    }
}

// ================= host driver =================
struct Scratch {
    __nv_bfloat16 *nxh, *nxl, *hh, *hl, *ctxh, *ctxl, *mhah, *mhal, *n2h, *n2l, *ff1h, *ff1l;
    __nv_bfloat16 *winth, *wintl, *wqkvth, *wqkvtl, *woth, *wotl, *w2th, *w2tl, *wf1th, *wf1tl, *wf2th, *wf2tl;
    float *qkv, *p1, *n2, *attn, *bqkv;
};

static Scratch get_scratch() {
    static Scratch s = [] {
        Scratch t;
        void* p;
        cudaGetSymbolAddress(&p, g_nx_h);   t.nxh = (__nv_bfloat16*)p;
        cudaGetSymbolAddress(&p, g_nx_l);   t.nxl = (__nv_bfloat16*)p;
        cudaGetSymbolAddress(&p, g_h_h);    t.hh  = (__nv_bfloat16*)p;
        cudaGetSymbolAddress(&p, g_h_l);    t.hl  = (__nv_bfloat16*)p;
        cudaGetSymbolAddress(&p, g_ctx_h);  t.ctxh = (__nv_bfloat16*)p;
        cudaGetSymbolAddress(&p, g_ctx_l);  t.ctxl = (__nv_bfloat16*)p;
        cudaGetSymbolAddress(&p, g_mha_h);  t.mhah = (__nv_bfloat16*)p;
        cudaGetSymbolAddress(&p, g_mha_l);  t.mhal = (__nv_bfloat16*)p;
        cudaGetSymbolAddress(&p, g_n2_h);   t.n2h = (__nv_bfloat16*)p;
        cudaGetSymbolAddress(&p, g_n2_l);   t.n2l = (__nv_bfloat16*)p;
        cudaGetSymbolAddress(&p, g_ff1_h);  t.ff1h = (__nv_bfloat16*)p;
        cudaGetSymbolAddress(&p, g_ff1_l);  t.ff1l = (__nv_bfloat16*)p;
        cudaGetSymbolAddress(&p, g_wint_h); t.winth = (__nv_bfloat16*)p;
        cudaGetSymbolAddress(&p, g_wint_l); t.wintl = (__nv_bfloat16*)p;
        cudaGetSymbolAddress(&p, g_wqkvt_h); t.wqkvth = (__nv_bfloat16*)p;
        cudaGetSymbolAddress(&p, g_wqkvt_l); t.wqkvtl = (__nv_bfloat16*)p;
        cudaGetSymbolAddress(&p, g_wot_h);  t.woth = (__nv_bfloat16*)p;
        cudaGetSymbolAddress(&p, g_wot_l);  t.wotl = (__nv_bfloat16*)p;
        cudaGetSymbolAddress(&p, g_w2t_h);  t.w2th = (__nv_bfloat16*)p;
        cudaGetSymbolAddress(&p, g_w2t_l);  t.w2tl = (__nv_bfloat16*)p;
        cudaGetSymbolAddress(&p, g_wf1t_h); t.wf1th = (__nv_bfloat16*)p;
        cudaGetSymbolAddress(&p, g_wf1t_l); t.wf1tl = (__nv_bfloat16*)p;
        cudaGetSymbolAddress(&p, g_wf2t_h); t.wf2th = (__nv_bfloat16*)p;
        cudaGetSymbolAddress(&p, g_wf2t_l); t.wf2tl = (__nv_bfloat16*)p;
        cudaGetSymbolAddress(&p, g_qkv);    t.qkv = (float*)p;
        cudaGetSymbolAddress(&p, g_p1);     t.p1  = (float*)p;
        cudaGetSymbolAddress(&p, g_n2);     t.n2  = (float*)p;
        cudaGetSymbolAddress(&p, g_attn_scratch); t.attn = (float*)p;
        cudaGetSymbolAddress(&p, g_bqkv);   t.bqkv = (float*)p;
        cudaFuncSetAttribute((const void*)mma_gemm<0,1,0,0>, cudaFuncAttributeMaxDynamicSharedMemorySize, MMA_SMEM);
        cudaFuncSetAttribute((const void*)mma_gemm<1,0,0,0>, cudaFuncAttributeMaxDynamicSharedMemorySize, MMA_SMEM);
        cudaFuncSetAttribute((const void*)mma_gemm<1,0,0,1>, cudaFuncAttributeMaxDynamicSharedMemorySize, MMA_SMEM);
        cudaFuncSetAttribute((const void*)mma_gemm<0,1,1,0>, cudaFuncAttributeMaxDynamicSharedMemorySize, MMA_SMEM);
        return t;
    }();
    return s;
}

extern "C" void kernel_launch(void* const* d_in, const int* in_sizes, int n_in,
                              void* d_out, int out_size)
{
    const float* x     = (const float*)d_in[0];
    const float* g1    = (const float*)d_in[1];
    const float* beta1 = (const float*)d_in[2];
    const float* W_in  = (const float*)d_in[3];
    const float* b_in  = (const float*)d_in[4];
    const float* Wq    = (const float*)d_in[5];
    const float* bq    = (const float*)d_in[6];
    const float* Wk    = (const float*)d_in[7];
    const float* bk    = (const float*)d_in[8];
    const float* Wv    = (const float*)d_in[9];
    const float* bv    = (const float*)d_in[10];
    const float* Wo    = (const float*)d_in[11];
    const float* bo    = (const float*)d_in[12];
    const float* W2    = (const float*)d_in[13];
    const float* b2    = (const float*)d_in[14];
    const float* g2    = (const float*)d_in[15];
    const float* beta2 = (const float*)d_in[16];
    const float* Wf1   = (const float*)d_in[17];
    const float* bf1   = (const float*)d_in[18];
    const float* Wf2   = (const float*)d_in[19];
    const float* bf2   = (const float*)d_in[20];

    Scratch s = get_scratch();

    float* out  = (float*)d_out;
    const long long full = (long long)SQ * D + (long long)NH * SQ * SQ;
    float* attn = ((long long)out_size >= full) ? (out + (size_t)SQ * D) : s.attn;

    dim3 blk(256);
    dim3 wblk(32, 8);

    // weight prep (transpose + bf16 hi/lo split)
    wprep_kernel<<<dim3(D/32,  D/32),   wblk>>>(W_in, s.winth, s.wintl, D,   D,   0);
    wprep_kernel<<<dim3(D/32,  D/32),   wblk>>>(Wq,   s.wqkvth, s.wqkvtl, D, D,   0);
    wprep_kernel<<<dim3(D/32,  D/32),   wblk>>>(Wk,   s.wqkvth, s.wqkvtl, D, D,   D);
    wprep_kernel<<<dim3(D/32,  D/32),   wblk>>>(Wv,   s.wqkvth, s.wqkvtl, D, D,   2*D);
    wprep_kernel<<<dim3(D/32,  D/32),   wblk>>>(Wo,   s.woth, s.wotl, D,   D,   0);
    wprep_kernel<<<dim3(D/32,  D/32),   wblk>>>(W2,   s.w2th, s.w2tl, D,   D,   0);
    wprep_kernel<<<dim3(DFF/32, D/32),  wblk>>>(Wf1,  s.wf1th, s.wf1tl, D, DFF, 0);
    wprep_kernel<<<dim3(D/32,  DFF/32), wblk>>>(Wf2,  s.wf2th, s.wf2tl, DFF, D, 0);
    cudaMemcpyAsync(s.bqkv,         bq, D * sizeof(float), cudaMemcpyDeviceToDevice, 0);
    cudaMemcpyAsync(s.bqkv + D,     bk, D * sizeof(float), cudaMemcpyDeviceToDevice, 0);
    cudaMemcpyAsync(s.bqkv + 2 * D, bv, D * sizeof(float), cudaMemcpyDeviceToDevice, 0);

    // 1. LN1 -> split only
    ln_kernel<0,1><<<SQ, blk>>>(x, g1, beta1, nullptr, s.nxh, s.nxl);
    // 2. h = nx @ W_in + b_in -> split only
    mma_gemm<0,1,0,0><<<dim3(D/128, SQ/128), 256, MMA_SMEM>>>(
        s.nxh, s.nxl, s.winth, s.wintl, b_in, nullptr, nullptr, s.hh, s.hl, D, D);
    // 3. qkv (packed N=3072) -> fp32
    mma_gemm<1,0,0,0><<<dim3(3*D/128, SQ/128), 256, MMA_SMEM>>>(
        s.hh, s.hl, s.wqkvth, s.wqkvtl, s.bqkv, nullptr, s.qkv, nullptr, nullptr, 3*D, D);
    // 4-6. attention
    score_kernel<<<dim3(SQ/128, SQ/128, NH), blk>>>(s.qkv, s.qkv + D, attn, 3*D);
    softmax_kernel<<<dim3(SQ, NH), blk>>>(attn);
    av_kernel<<<dim3(SQ/128, NH), blk>>>(attn, s.qkv + 2*D, s.ctxh, s.ctxl, 3*D);
    // 7. mha = ctx @ Wo + bo -> split only
    mma_gemm<0,1,0,0><<<dim3(D/128, SQ/128), 256, MMA_SMEM>>>(
        s.ctxh, s.ctxl, s.woth, s.wotl, bo, nullptr, nullptr, s.mhah, s.mhal, D, D);
    // 8. p1 = x + mha @ W2 + b2 -> fp32
    mma_gemm<1,0,0,1><<<dim3(D/128, SQ/128), 256, MMA_SMEM>>>(
        s.mhah, s.mhal, s.w2th, s.w2tl, b2, x, s.p1, nullptr, nullptr, D, D);
    // 9. LN2 -> fp32 + split
    ln_kernel<1,1><<<SQ, blk>>>(s.p1, g2, beta2, s.n2, s.n2h, s.n2l);
    // 10. ff1 = relu(n2 @ Wf1 + bf1) -> split only
    mma_gemm<0,1,1,0><<<dim3(DFF/128, SQ/128), 256, MMA_SMEM>>>(
        s.n2h, s.n2l, s.wf1th, s.wf1tl, bf1, nullptr, nullptr, s.ff1h, s.ff1l, DFF, D);
    // 11. out = n2 + ff1 @ Wf2 + bf2 -> fp32
    mma_gemm<1,0,0,1><<<dim3(D/128, SQ/128), 256, MMA_SMEM>>>(
        s.ff1h, s.ff1l, s.wf2th, s.wf2tl, bf2, s.n2, out, nullptr, nullptr, D, DFF);
}

// round 6
// speedup vs baseline: 4.0031x; 1.3091x over previous
#include <cuda_runtime.h>
#include <cuda_bf16.h>
#include <math.h>
#include <stdint.h>

#define SQ   2048
#define D    1024
#define NH   16
#define DK   64
#define DFF  4096

// ================= PTX helpers (baseline ISA only) ==========================
__device__ __forceinline__ uint32_t smem_u32(const void* p) {
    uint32_t a;
    asm("{ .reg .u64 t; cvta.to.shared.u64 t, %1; cvt.u32.u64 %0, t; }" : "=r"(a) : "l"(p));
    return a;
}
__device__ __forceinline__ void cpa16(uint32_t dst, const void* src) {
    asm volatile("cp.async.cg.shared.global [%0], [%1], 16;" :: "r"(dst), "l"(src));
}
#define CPA_COMMIT() asm volatile("cp.async.commit_group;" ::: "memory")
__device__ __forceinline__ void ldm_x4(uint32_t& r0, uint32_t& r1, uint32_t& r2, uint32_t& r3, uint32_t addr) {
    asm volatile("ldmatrix.sync.aligned.m8n8.x4.shared.b16 {%0,%1,%2,%3}, [%4];"
                 : "=r"(r0), "=r"(r1), "=r"(r2), "=r"(r3) : "r"(addr));
}
__device__ __forceinline__ void ldm_x2(uint32_t& r0, uint32_t& r1, uint32_t addr) {
    asm volatile("ldmatrix.sync.aligned.m8n8.x2.shared.b16 {%0,%1}, [%2];"
                 : "=r"(r0), "=r"(r1) : "r"(addr));
}
__device__ __forceinline__ void ldm_x2t(uint32_t& r0, uint32_t& r1, uint32_t addr) {
    asm volatile("ldmatrix.sync.aligned.m8n8.x2.trans.shared.b16 {%0,%1}, [%2];"
                 : "=r"(r0), "=r"(r1) : "r"(addr));
}
__device__ __forceinline__ void mma_bf16(float* c, uint32_t a0, uint32_t a1, uint32_t a2, uint32_t a3,
                                         uint32_t b0, uint32_t b1) {
    asm volatile("mma.sync.aligned.m16n8k16.row.col.f32.bf16.bf16.f32 "
                 "{%0,%1,%2,%3}, {%4,%5,%6,%7}, {%8,%9}, {%0,%1,%2,%3};"
                 : "+f"(c[0]), "+f"(c[1]), "+f"(c[2]), "+f"(c[3])
                 : "r"(a0), "r"(a1), "r"(a2), "r"(a3), "r"(b0), "r"(b1));
}

// ================= scratch =================
__device__ __nv_bfloat16 g_nx_h[SQ * D],  g_nx_l[SQ * D];
__device__ __nv_bfloat16 g_h_h[SQ * D],   g_h_l[SQ * D];
__device__ __nv_bfloat16 g_qkv_h[SQ * 3 * D], g_qkv_l[SQ * 3 * D];
__device__ __nv_bfloat16 g_ctx_h[SQ * D], g_ctx_l[SQ * D];
__device__ __nv_bfloat16 g_mha_h[SQ * D], g_mha_l[SQ * D];
__device__ float         g_p1[SQ * D];
__device__ float         g_n2[SQ * D];
__device__ __nv_bfloat16 g_n2_h[SQ * D],  g_n2_l[SQ * D];
__device__ __nv_bfloat16 g_ff1_h[SQ * DFF], g_ff1_l[SQ * DFF];
__device__ float         g_attn_scratch[(size_t)NH * SQ * SQ];
__device__ __nv_bfloat16 g_attn_h[(size_t)NH * SQ * SQ];
__device__ __nv_bfloat16 g_attn_l[(size_t)NH * SQ * SQ];
// transposed/split weights [N, K]
__device__ __nv_bfloat16 g_wint_h[D * D],      g_wint_l[D * D];
__device__ __nv_bfloat16 g_wqkvt_h[3 * D * D], g_wqkvt_l[3 * D * D];
__device__ __nv_bfloat16 g_wot_h[D * D],       g_wot_l[D * D];
__device__ __nv_bfloat16 g_w2t_h[D * D],       g_w2t_l[D * D];
__device__ __nv_bfloat16 g_wf1t_h[DFF * D],    g_wf1t_l[DFF * D];
__device__ __nv_bfloat16 g_wf2t_h[D * DFF],    g_wf2t_l[D * DFF];
__device__ float         g_bqkv[3 * D];

// ================= weight prep: W[K,N] fp32 -> T[N,K] bf16 hi/lo =============
__global__ __launch_bounds__(256) void wprep_kernel(
    const float* __restrict__ W, __nv_bfloat16* __restrict__ Th,
    __nv_bfloat16* __restrict__ Tl, int K, int N, int rowoff)
{
    __shared__ float t[32][33];
    const int n0 = blockIdx.x * 32, k0 = blockIdx.y * 32;
    const int tx = threadIdx.x, ty = threadIdx.y;
    for (int i = ty; i < 32; i += 8)
        t[i][tx] = W[(size_t)(k0 + i) * N + n0 + tx];
    __syncthreads();
    for (int i = ty; i < 32; i += 8) {
        float v = t[tx][i];
        __nv_bfloat16 h = __float2bfloat16_rn(v);
        size_t o = (size_t)(rowoff + n0 + i) * K + k0 + tx;
        Th[o] = h;
        Tl[o] = __float2bfloat16_rn(v - __bfloat162float(h));
    }
}

// ================= LayerNorm ========
template<int WF32, int WSPLIT>
__global__ __launch_bounds__(256) void ln_kernel(
    const float* __restrict__ x, const float* __restrict__ g,
    const float* __restrict__ b, float* __restrict__ outf,
    __nv_bfloat16* __restrict__ oh, __nv_bfloat16* __restrict__ ol)
{
    __shared__ float red[256];
    const int row = blockIdx.x;
    const int tid = threadIdx.x;
    float4 v = *(const float4*)(x + (size_t)row * D + tid * 4);
    red[tid] = v.x + v.y + v.z + v.w;
    __syncthreads();
    for (int o = 128; o > 0; o >>= 1) { if (tid < o) red[tid] += red[tid + o]; __syncthreads(); }
    const float mean = red[0] * (1.0f / D);
    __syncthreads();
    const float dx = v.x - mean, dy = v.y - mean, dz = v.z - mean, dw = v.w - mean;
    red[tid] = dx * dx + dy * dy + dz * dz + dw * dw;
    __syncthreads();
    for (int o = 128; o > 0; o >>= 1) { if (tid < o) red[tid] += red[tid + o]; __syncthreads(); }
    const float inv = 1.0f / (sqrtf(red[0] * (1.0f / D)) + 1e-6f);
    float4 gg = *(const float4*)(g + tid * 4);
    float4 bb = *(const float4*)(b + tid * 4);
    float o0 = gg.x * dx * inv + bb.x;
    float o1 = gg.y * dy * inv + bb.y;
    float o2 = gg.z * dz * inv + bb.z;
    float o3 = gg.w * dw * inv + bb.w;
    const size_t base = (size_t)row * D + tid * 4;
    if (WF32) {
        float4 o4 = {o0, o1, o2, o3};
        *(float4*)(outf + base) = o4;
    }
    if (WSPLIT) {
        float vv[4] = {o0, o1, o2, o3};
        __nv_bfloat16 hs[4], ls[4];
#pragma unroll
        for (int i = 0; i < 4; i++) {
            hs[i] = __float2bfloat16_rn(vv[i]);
            ls[i] = __float2bfloat16_rn(vv[i] - __bfloat162float(hs[i]));
        }
        *(uint2*)(oh + base) = *(uint2*)hs;
        *(uint2*)(ol + base) = *(uint2*)ls;
    }
}

// ================= shared GEMM plumbing ======================================
#define STG_A_H 0
#define STG_A_L 8192
#define STG_B_H 16384
#define STG_B_L 24576
#define STG_SZ  32768
#define MMA_SMEM (2 * STG_SZ)

// swizzled byte offset for (row, kb16) in a [rows][32] bf16 tile (64B rows)
__device__ __forceinline__ uint32_t swz(int row, int kb) {
    return (uint32_t)(row * 64 + ((kb ^ ((row >> 1) & 3)) << 4));
}

__device__ __forceinline__ void load_tile(
    const __nv_bfloat16* __restrict__ g, int ld, int row0, int k0, uint32_t sbase, int tid)
{
#pragma unroll
    for (int it = 0; it < 2; it++) {
        int c = tid + (it << 8);   // 0..511
        int row = c >> 2, kb = c & 3;
        cpa16(sbase + swz(row, kb), g + (size_t)(row0 + row) * ld + k0 + kb * 8);
    }
}

// ================= mma.sync GEMM: C[M,N] = A[M,K] @ T[N,K]^T =================
template<int WF32, int WSPLIT, int RELU, int RESID>
__global__ __launch_bounds__(256, 1) void mma_gemm(
    const __nv_bfloat16* __restrict__ Ah, const __nv_bfloat16* __restrict__ Al,
    const __nv_bfloat16* __restrict__ Bh, const __nv_bfloat16* __restrict__ Bl,
    const float* __restrict__ bias, const float* __restrict__ res,
    float* __restrict__ Cf, __nv_bfloat16* __restrict__ Chi, __nv_bfloat16* __restrict__ Clo,
    int N, int K)
{
    extern __shared__ char smem[];
    const uint32_t sb = smem_u32(smem);
    const int tid = threadIdx.x, wid = tid >> 5, lane = tid & 31;
    const int warp_m = wid & 1;
    const int warp_n = wid >> 1;
    const int brow = blockIdx.y * 128, bcol = blockIdx.x * 128;

    float acc[4][4][4];
#pragma unroll
    for (int a = 0; a < 4; a++)
#pragma unroll
        for (int b = 0; b < 4; b++)
#pragma unroll
            for (int c = 0; c < 4; c++) acc[a][b][c] = 0.0f;

    load_tile(Ah, K, brow, 0, sb + STG_A_H, tid);
    load_tile(Al, K, brow, 0, sb + STG_A_L, tid);
    load_tile(Bh, K, bcol, 0, sb + STG_B_H, tid);
    load_tile(Bl, K, bcol, 0, sb + STG_B_L, tid);
    CPA_COMMIT();

    const int tileA = lane >> 3;
    const int rinA  = (lane & 7) + ((tileA & 1) << 3);
    const int kbA   = tileA >> 1;
    const int i16   = lane & 15;
    const int rinB  = i16 & 7;
    const int kbB   = i16 >> 3;

    const int nch = K >> 5;
    for (int i = 0; i < nch; i++) {
        if (i + 1 < nch) {
            const uint32_t st = sb + ((i + 1) & 1) * STG_SZ;
            const int k0 = (i + 1) << 5;
            load_tile(Ah, K, brow, k0, st + STG_A_H, tid);
            load_tile(Al, K, brow, k0, st + STG_A_L, tid);
            load_tile(Bh, K, bcol, k0, st + STG_B_H, tid);
            load_tile(Bl, K, bcol, k0, st + STG_B_L, tid);
            CPA_COMMIT();
            asm volatile("cp.async.wait_group 1;" ::: "memory");
        } else {
            asm volatile("cp.async.wait_group 0;" ::: "memory");
        }
        __syncthreads();

        const uint32_t st = sb + (i & 1) * STG_SZ;
#pragma unroll
        for (int ks = 0; ks < 2; ks++) {
            uint32_t bh[4][2], bl[4][2];
#pragma unroll
            for (int nt = 0; nt < 4; nt++) {
                const int rowb = warp_n * 32 + nt * 8 + rinB;
                const uint32_t off = swz(rowb, (ks << 1) + kbB);
                ldm_x2(bh[nt][0], bh[nt][1], st + STG_B_H + off);
                ldm_x2(bl[nt][0], bl[nt][1], st + STG_B_L + off);
            }
#pragma unroll
            for (int mt = 0; mt < 4; mt++) {
                const int rowa = warp_m * 64 + mt * 16 + rinA;
                const uint32_t off = swz(rowa, (ks << 1) + kbA);
                uint32_t a0, a1, a2, a3, l0, l1, l2, l3;
                ldm_x4(a0, a1, a2, a3, st + STG_A_H + off);
                ldm_x4(l0, l1, l2, l3, st + STG_A_L + off);
#pragma unroll
                for (int nt = 0; nt < 4; nt++) {
                    mma_bf16(acc[mt][nt], a0, a1, a2, a3, bh[nt][0], bh[nt][1]);
                    mma_bf16(acc[mt][nt], a0, a1, a2, a3, bl[nt][0], bl[nt][1]);
                    mma_bf16(acc[mt][nt], l0, l1, l2, l3, bh[nt][0], bh[nt][1]);
                }
            }
        }
        __syncthreads();
    }

    const int g4 = lane >> 2, t4 = lane & 3;
#pragma unroll
    for (int mt = 0; mt < 4; mt++) {
#pragma unroll
        for (int half = 0; half < 2; half++) {
            const int row = brow + warp_m * 64 + mt * 16 + g4 + half * 8;
#pragma unroll
            for (int nt = 0; nt < 4; nt++) {
                const int col = bcol + warp_n * 32 + nt * 8 + t4 * 2;
                float v0 = acc[mt][nt][half * 2 + 0] + bias[col];
                float v1 = acc[mt][nt][half * 2 + 1] + bias[col + 1];
                if (RELU) { v0 = fmaxf(v0, 0.0f); v1 = fmaxf(v1, 0.0f); }
                const size_t o = (size_t)row * N + col;
                if (RESID) { v0 += res[o]; v1 += res[o + 1]; }
                if (WF32) {
                    float2 f2 = {v0, v1};
                    *(float2*)(Cf + o) = f2;
                }
                if (WSPLIT) {
                    __nv_bfloat16 h0 = __float2bfloat16_rn(v0);
                    __nv_bfloat16 h1 = __float2bfloat16_rn(v1);
                    __nv_bfloat16 q0 = __float2bfloat16_rn(v0 - __bfloat162float(h0));
                    __nv_bfloat16 q1 = __float2bfloat16_rn(v1 - __bfloat162float(h1));
                    __nv_bfloat162 hp = {h0, h1}, lp = {q0, q1};
                    *(__nv_bfloat162*)(Chi + o) = hp;
                    *(__nv_bfloat162*)(Clo + o) = lp;
                }
            }
        }
    }
}

// ================= score mma: S = (Q K^T)/8, causal ==========================
// A = q split (ld 3*D), B = k split (ld 3*D), K-dim = DK=64. Writes fp32 lower triangle.
__global__ __launch_bounds__(256, 1) void score_mma(
    const __nv_bfloat16* __restrict__ qh, const __nv_bfloat16* __restrict__ ql,
    const __nv_bfloat16* __restrict__ kh, const __nv_bfloat16* __restrict__ kl,
    float* __restrict__ attn)
{
    const int brow = blockIdx.y * 128, bcol = blockIdx.x * 128;
    if (bcol >= brow + 128) return;
    const int h = blockIdx.z;
    const __nv_bfloat16* Ah = qh + h * DK;
    const __nv_bfloat16* Al = ql + h * DK;
    const __nv_bfloat16* Bh = kh + h * DK;
    const __nv_bfloat16* Bl = kl + h * DK;

    extern __shared__ char smem[];
    const uint32_t sb = smem_u32(smem);
    const int tid = threadIdx.x, wid = tid >> 5, lane = tid & 31;
    const int warp_m = wid & 1, warp_n = wid >> 1;

    float acc[4][4][4];
#pragma unroll
    for (int a = 0; a < 4; a++)
#pragma unroll
        for (int b = 0; b < 4; b++)
#pragma unroll
            for (int c = 0; c < 4; c++) acc[a][b][c] = 0.0f;

    load_tile(Ah, 3 * D, brow, 0, sb + STG_A_H, tid);
    load_tile(Al, 3 * D, brow, 0, sb + STG_A_L, tid);
    load_tile(Bh, 3 * D, bcol, 0, sb + STG_B_H, tid);
    load_tile(Bl, 3 * D, bcol, 0, sb + STG_B_L, tid);
    CPA_COMMIT();

    const int tileA = lane >> 3;
    const int rinA  = (lane & 7) + ((tileA & 1) << 3);
    const int kbA   = tileA >> 1;
    const int i16   = lane & 15;
    const int rinB  = i16 & 7;
    const int kbB   = i16 >> 3;

    for (int i = 0; i < 2; i++) {
        if (i == 0) {
            const uint32_t st = sb + STG_SZ;
            load_tile(Ah, 3 * D, brow, 32, st + STG_A_H, tid);
            load_tile(Al, 3 * D, brow, 32, st + STG_A_L, tid);
            load_tile(Bh, 3 * D, bcol, 32, st + STG_B_H, tid);
            load_tile(Bl, 3 * D, bcol, 32, st + STG_B_L, tid);
            CPA_COMMIT();
            asm volatile("cp.async.wait_group 1;" ::: "memory");
        } else {
            asm volatile("cp.async.wait_group 0;" ::: "memory");
        }
        __syncthreads();

        const uint32_t st = sb + (i & 1) * STG_SZ;
#pragma unroll
        for (int ks = 0; ks < 2; ks++) {
            uint32_t bh[4][2], bl[4][2];
#pragma unroll
            for (int nt = 0; nt < 4; nt++) {
                const int rowb = warp_n * 32 + nt * 8 + rinB;
                const uint32_t off = swz(rowb, (ks << 1) + kbB);
                ldm_x2(bh[nt][0], bh[nt][1], st + STG_B_H + off);
                ldm_x2(bl[nt][0], bl[nt][1], st + STG_B_L + off);
            }
#pragma unroll
            for (int mt = 0; mt < 4; mt++) {
                const int rowa = warp_m * 64 + mt * 16 + rinA;
                const uint32_t off = swz(rowa, (ks << 1) + kbA);
                uint32_t a0, a1, a2, a3, l0, l1, l2, l3;
                ldm_x4(a0, a1, a2, a3, st + STG_A_H + off);
                ldm_x4(l0, l1, l2, l3, st + STG_A_L + off);
#pragma unroll
                for (int nt = 0; nt < 4; nt++) {
                    mma_bf16(acc[mt][nt], a0, a1, a2, a3, bh[nt][0], bh[nt][1]);
                    mma_bf16(acc[mt][nt], a0, a1, a2, a3, bl[nt][0], bl[nt][1]);
                    mma_bf16(acc[mt][nt], l0, l1, l2, l3, bh[nt][0], bh[nt][1]);
                }
            }
        }
        __syncthreads();
    }

    const int g4 = lane >> 2, t4 = lane & 3;
#pragma unroll
    for (int mt = 0; mt < 4; mt++) {
#pragma unroll
        for (int half = 0; half < 2; half++) {
            const int row = brow + warp_m * 64 + mt * 16 + g4 + half * 8;
            float* arow = attn + ((size_t)h * SQ + row) * SQ;
#pragma unroll
            for (int nt = 0; nt < 4; nt++) {
                const int col = bcol + warp_n * 32 + nt * 8 + t4 * 2;
                if (col <= row)     arow[col]     = acc[mt][nt][half * 2 + 0] * 0.125f;
                if (col + 1 <= row) arow[col + 1] = acc[mt][nt][half * 2 + 1] * 0.125f;
            }
        }
    }
}

// ================= softmax: fp32 out + bf16 hi/lo split ======================
__global__ __launch_bounds__(256) void softmax_kernel(
    float* __restrict__ attn,
    __nv_bfloat16* __restrict__ ah, __nv_bfloat16* __restrict__ al)
{
    __shared__ float p[SQ];
    __shared__ float red[256];
    const int i   = blockIdx.x;
    const int h   = blockIdx.y;
    const int tid = threadIdx.x;
    const size_t rb = ((size_t)h * SQ + i) * SQ;
    float* row = attn + rb;

    float m = -INFINITY;
    for (int j = tid; j <= i; j += 256) { float s = row[j]; p[j] = s; m = fmaxf(m, s); }
    red[tid] = m;
    __syncthreads();
    for (int o = 128; o > 0; o >>= 1) { if (tid < o) red[tid] = fmaxf(red[tid], red[tid + o]); __syncthreads(); }
    const float mx = red[0];
    __syncthreads();

    float sum = 0.0f;
    for (int j = tid; j <= i; j += 256) { float e = __expf(p[j] - mx); p[j] = e; sum += e; }
    red[tid] = sum;
    __syncthreads();
    for (int o = 128; o > 0; o >>= 1) { if (tid < o) red[tid] += red[tid + o]; __syncthreads(); }
    const float inv = 1.0f / red[0];
    __syncthreads();

    const int lim = ((i >> 7) + 1) << 7;   // AV never reads past this
    for (int j = tid; j <= i; j += 256) {
        float w = p[j] * inv;
        row[j] = w;
        __nv_bfloat16 hh = __float2bfloat16_rn(w);
        ah[rb + j] = hh;
        al[rb + j] = __float2bfloat16_rn(w - __bfloat162float(hh));
    }
    for (int j = i + 1 + tid; j < SQ; j += 256) row[j] = 0.0f;
    const __nv_bfloat16 z = __float2bfloat16_rn(0.0f);
    for (int j = i + 1 + tid; j < lim; j += 256) { ah[rb + j] = z; al[rb + j] = z; }
}

// ================= AV mma: ctx = P @ V ======================================
// A = attn split [i, j] (ld SQ); B = v rows [j, d] (d contiguous, ld 3D) via ldmatrix.trans.
#define AV_A_H 0
#define AV_A_L 8192
#define AV_B_H 16384
#define AV_B_L 20480
#define AV_STG 24576
#define AV_SMEM (2 * AV_STG)

__global__ __launch_bounds__(256, 1) void av_mma(
    const __nv_bfloat16* __restrict__ ah, const __nv_bfloat16* __restrict__ al,
    const __nv_bfloat16* __restrict__ vh, const __nv_bfloat16* __restrict__ vl,
    __nv_bfloat16* __restrict__ ch, __nv_bfloat16* __restrict__ cl)
{
    const int brow = blockIdx.x * 128;
    const int h    = blockIdx.y;
    const __nv_bfloat16* Ah = ah + (size_t)h * SQ * SQ;
    const __nv_bfloat16* Al = al + (size_t)h * SQ * SQ;
    const __nv_bfloat16* Vh = vh + 2 * D + h * DK;    // packed qkv layout
    const __nv_bfloat16* Vl = vl + 2 * D + h * DK;

    extern __shared__ char smem[];
    const uint32_t sb = smem_u32(smem);
    const int tid = threadIdx.x, wid = tid >> 5, lane = tid & 31;
    const int warp_m = wid & 3;     // 4 x 32 rows
    const int warp_n = wid >> 2;    // 2 x 32 cols

    float acc[2][4][4];
#pragma unroll
    for (int a = 0; a < 2; a++)
#pragma unroll
        for (int b = 0; b < 4; b++)
#pragma unroll
            for (int c = 0; c < 4; c++) acc[a][b][c] = 0.0f;

    // B tile loader: [32 k-rows][64 d] bf16, 128B rows, granule-xor swizzle
    auto load_b = [&](const __nv_bfloat16* V, int k0, uint32_t sbase) {
        int r = tid >> 3, g = tid & 7;
        cpa16(sbase + (uint32_t)(r * 128 + ((g ^ (r & 7)) << 4)),
              V + (size_t)(k0 + r) * (3 * D) + g * 8);
    };

    load_tile(Ah, SQ, brow, 0, sb + AV_A_H, tid);
    load_tile(Al, SQ, brow, 0, sb + AV_A_L, tid);
    load_b(Vh, 0, sb + AV_B_H);
    load_b(Vl, 0, sb + AV_B_L);
    CPA_COMMIT();

    const int tileA = lane >> 3;
    const int rinA  = (lane & 7) + ((tileA & 1) << 3);
    const int kbA   = tileA >> 1;
    const int i16   = lane & 15;

    const int nch = (brow >> 5) + 4;
    for (int i = 0; i < nch; i++) {
        if (i + 1 < nch) {
            const uint32_t st = sb + ((i + 1) & 1) * AV_STG;
            const int k0 = (i + 1) << 5;
            load_tile(Ah, SQ, brow, k0, st + AV_A_H, tid);
            load_tile(Al, SQ, brow, k0, st + AV_A_L, tid);
            load_b(Vh, k0, st + AV_B_H);
            load_b(Vl, k0, st + AV_B_L);
            CPA_COMMIT();
            asm volatile("cp.async.wait_group 1;" ::: "memory");
        } else {
            asm volatile("cp.async.wait_group 0;" ::: "memory");
        }
        __syncthreads();

        const uint32_t st = sb + (i & 1) * AV_STG;
#pragma unroll
        for (int ks = 0; ks < 2; ks++) {
            uint32_t bh[4][2], bl[4][2];
#pragma unroll
            for (int nt = 0; nt < 4; nt++) {
                const int krow = ks * 16 + i16;
                const int gB = warp_n * 4 + nt;
                const uint32_t off = (uint32_t)(krow * 128 + ((gB ^ (krow & 7)) << 4));
                ldm_x2t(bh[nt][0], bh[nt][1], st + AV_B_H + off);
                ldm_x2t(bl[nt][0], bl[nt][1], st + AV_B_L + off);
            }
#pragma unroll
            for (int mt = 0; mt < 2; mt++) {
                const int rowa = warp_m * 32 + mt * 16 + rinA;
                const uint32_t off = swz(rowa, (ks << 1) + kbA);
                uint32_t a0, a1, a2, a3, l0, l1, l2, l3;
                ldm_x4(a0, a1, a2, a3, st + AV_A_H + off);
                ldm_x4(l0, l1, l2, l3, st + AV_A_L + off);
#pragma unroll
                for (int nt = 0; nt < 4; nt++) {
                    mma_bf16(acc[mt][nt], a0, a1, a2, a3, bh[nt][0], bh[nt][1]);
                    mma_bf16(acc[mt][nt], a0, a1, a2, a3, bl[nt][0], bl[nt][1]);
                    mma_bf16(acc[mt][nt], l0, l1, l2, l3, bh[nt][0], bh[nt][1]);
                }
            }
        }
        __syncthreads();
    }

    const int g4 = lane >> 2, t4 = lane & 3;
#pragma unroll
    for (int mt = 0; mt < 2; mt++) {
#pragma unroll
        for (int half = 0; half < 2; half++) {
            const int row = brow + warp_m * 32 + mt * 16 + g4 + half * 8;
#pragma unroll
            for (int nt = 0; nt < 4; nt++) {
                const int col = h * DK + warp_n * 32 + nt * 8 + t4 * 2;
                float v0 = acc[mt][nt][half * 2 + 0];
                float v1 = acc[mt][nt][half * 2 + 1];
                const size_t o = (size_t)row * D + col;
                __nv_bfloat16 h0 = __float2bfloat16_rn(v0);
                __nv_bfloat16 h1 = __float2bfloat16_rn(v1);
                __nv_bfloat16 q0 = __float2bfloat16_rn(v0 - __bfloat162float(h0));
                __nv_bfloat16 q1 = __float2bfloat16_rn(v1 - __bfloat162float(h1));
                __nv_bfloat162 hp = {h0, h1}, lp = {q0, q1};
                *(__nv_bfloat162*)(ch + o) = hp;
                *(__nv_bfloat162*)(cl + o) = lp;
            }
        }
    }
}

// ================= host driver =================
struct Scratch {
    __nv_bfloat16 *nxh, *nxl, *hh, *hl, *qkvh, *qkvl, *ctxh, *ctxl, *mhah, *mhal, *n2h, *n2l, *ff1h, *ff1l;
    __nv_bfloat16 *attnh, *attnl;
    __nv_bfloat16 *winth, *wintl, *wqkvth, *wqkvtl, *woth, *wotl, *w2th, *w2tl, *wf1th, *wf1tl, *wf2th, *wf2tl;
    float *p1, *n2, *attn, *bqkv;
};

static Scratch get_scratch() {
    static Scratch s = [] {
        Scratch t;
        void* p;
        cudaGetSymbolAddress(&p, g_nx_h);   t.nxh = (__nv_bfloat16*)p;
        cudaGetSymbolAddress(&p, g_nx_l);   t.nxl = (__nv_bfloat16*)p;
        cudaGetSymbolAddress(&p, g_h_h);    t.hh  = (__nv_bfloat16*)p;
        cudaGetSymbolAddress(&p, g_h_l);    t.hl  = (__nv_bfloat16*)p;
        cudaGetSymbolAddress(&p, g_qkv_h);  t.qkvh = (__nv_bfloat16*)p;
        cudaGetSymbolAddress(&p, g_qkv_l);  t.qkvl = (__nv_bfloat16*)p;
        cudaGetSymbolAddress(&p, g_ctx_h);  t.ctxh = (__nv_bfloat16*)p;
        cudaGetSymbolAddress(&p, g_ctx_l);  t.ctxl = (__nv_bfloat16*)p;
        cudaGetSymbolAddress(&p, g_mha_h);  t.mhah = (__nv_bfloat16*)p;
        cudaGetSymbolAddress(&p, g_mha_l);  t.mhal = (__nv_bfloat16*)p;
        cudaGetSymbolAddress(&p, g_n2_h);   t.n2h = (__nv_bfloat16*)p;
        cudaGetSymbolAddress(&p, g_n2_l);   t.n2l = (__nv_bfloat16*)p;
        cudaGetSymbolAddress(&p, g_ff1_h);  t.ff1h = (__nv_bfloat16*)p;
        cudaGetSymbolAddress(&p, g_ff1_l);  t.ff1l = (__nv_bfloat16*)p;
        cudaGetSymbolAddress(&p, g_attn_h); t.attnh = (__nv_bfloat16*)p;
        cudaGetSymbolAddress(&p, g_attn_l); t.attnl = (__nv_bfloat16*)p;
        cudaGetSymbolAddress(&p, g_wint_h); t.winth = (__nv_bfloat16*)p;
        cudaGetSymbolAddress(&p, g_wint_l); t.wintl = (__nv_bfloat16*)p;
        cudaGetSymbolAddress(&p, g_wqkvt_h); t.wqkvth = (__nv_bfloat16*)p;
        cudaGetSymbolAddress(&p, g_wqkvt_l); t.wqkvtl = (__nv_bfloat16*)p;
        cudaGetSymbolAddress(&p, g_wot_h);  t.woth = (__nv_bfloat16*)p;
        cudaGetSymbolAddress(&p, g_wot_l);  t.wotl = (__nv_bfloat16*)p;
        cudaGetSymbolAddress(&p, g_w2t_h);  t.w2th = (__nv_bfloat16*)p;
        cudaGetSymbolAddress(&p, g_w2t_l);  t.w2tl = (__nv_bfloat16*)p;
        cudaGetSymbolAddress(&p, g_wf1t_h); t.wf1th = (__nv_bfloat16*)p;
        cudaGetSymbolAddress(&p, g_wf1t_l); t.wf1tl = (__nv_bfloat16*)p;
        cudaGetSymbolAddress(&p, g_wf2t_h); t.wf2th = (__nv_bfloat16*)p;
        cudaGetSymbolAddress(&p, g_wf2t_l); t.wf2tl = (__nv_bfloat16*)p;
        cudaGetSymbolAddress(&p, g_p1);     t.p1  = (float*)p;
        cudaGetSymbolAddress(&p, g_n2);     t.n2  = (float*)p;
        cudaGetSymbolAddress(&p, g_attn_scratch); t.attn = (float*)p;
        cudaGetSymbolAddress(&p, g_bqkv);   t.bqkv = (float*)p;
        cudaFuncSetAttribute((const void*)mma_gemm<0,1,0,0>, cudaFuncAttributeMaxDynamicSharedMemorySize, MMA_SMEM);
        cudaFuncSetAttribute((const void*)mma_gemm<1,0,0,1>, cudaFuncAttributeMaxDynamicSharedMemorySize, MMA_SMEM);
        cudaFuncSetAttribute((const void*)mma_gemm<0,1,1,0>, cudaFuncAttributeMaxDynamicSharedMemorySize, MMA_SMEM);
        cudaFuncSetAttribute((const void*)score_mma, cudaFuncAttributeMaxDynamicSharedMemorySize, MMA_SMEM);
        cudaFuncSetAttribute((const void*)av_mma,    cudaFuncAttributeMaxDynamicSharedMemorySize, AV_SMEM);
        return t;
    }();
    return s;
}

extern "C" void kernel_launch(void* const* d_in, const int* in_sizes, int n_in,
                              void* d_out, int out_size)
{
    const float* x     = (const float*)d_in[0];
    const float* g1    = (const float*)d_in[1];
    const float* beta1 = (const float*)d_in[2];
    const float* W_in  = (const float*)d_in[3];
    const float* b_in  = (const float*)d_in[4];
    const float* Wq    = (const float*)d_in[5];
    const float* bq    = (const float*)d_in[6];
    const float* Wk    = (const float*)d_in[7];
    const float* bk    = (const float*)d_in[8];
    const float* Wv    = (const float*)d_in[9];
    const float* bv    = (const float*)d_in[10];
    const float* Wo    = (const float*)d_in[11];
    const float* bo    = (const float*)d_in[12];
    const float* W2    = (const float*)d_in[13];
    const float* b2    = (const float*)d_in[14];
    const float* g2    = (const float*)d_in[15];
    const float* beta2 = (const float*)d_in[16];
    const float* Wf1   = (const float*)d_in[17];
    const float* bf1   = (const float*)d_in[18];
    const float* Wf2   = (const float*)d_in[19];
    const float* bf2   = (const float*)d_in[20];

    Scratch s = get_scratch();

    float* out  = (float*)d_out;
    const long long full = (long long)SQ * D + (long long)NH * SQ * SQ;
    float* attn = ((long long)out_size >= full) ? (out + (size_t)SQ * D) : s.attn;

    dim3 blk(256);
    dim3 wblk(32, 8);

    wprep_kernel<<<dim3(D/32,  D/32),   wblk>>>(W_in, s.winth, s.wintl, D,   D,   0);
    wprep_kernel<<<dim3(D/32,  D/32),   wblk>>>(Wq,   s.wqkvth, s.wqkvtl, D, D,   0);
    wprep_kernel<<<dim3(D/32,  D/32),   wblk>>>(Wk,   s.wqkvth, s.wqkvtl, D, D,   D);
    wprep_kernel<<<dim3(D/32,  D/32),   wblk>>>(Wv,   s.wqkvth, s.wqkvtl, D, D,   2*D);
    wprep_kernel<<<dim3(D/32,  D/32),   wblk>>>(Wo,   s.woth, s.wotl, D,   D,   0);
    wprep_kernel<<<dim3(D/32,  D/32),   wblk>>>(W2,   s.w2th, s.w2tl, D,   D,   0);
    wprep_kernel<<<dim3(DFF/32, D/32),  wblk>>>(Wf1,  s.wf1th, s.wf1tl, D, DFF, 0);
    wprep_kernel<<<dim3(D/32,  DFF/32), wblk>>>(Wf2,  s.wf2th, s.wf2tl, DFF, D, 0);
    cudaMemcpyAsync(s.bqkv,         bq, D * sizeof(float), cudaMemcpyDeviceToDevice, 0);
    cudaMemcpyAsync(s.bqkv + D,     bk, D * sizeof(float), cudaMemcpyDeviceToDevice, 0);
    cudaMemcpyAsync(s.bqkv + 2 * D, bv, D * sizeof(float), cudaMemcpyDeviceToDevice, 0);

    // 1. LN1 -> split
    ln_kernel<0,1><<<SQ, blk>>>(x, g1, beta1, nullptr, s.nxh, s.nxl);
    // 2. h = nx @ W_in + b_in -> split
    mma_gemm<0,1,0,0><<<dim3(D/128, SQ/128), 256, MMA_SMEM>>>(
        s.nxh, s.nxl, s.winth, s.wintl, b_in, nullptr, nullptr, s.hh, s.hl, D, D);
    // 3. qkv (packed N=3072) -> split
    mma_gemm<0,1,0,0><<<dim3(3*D/128, SQ/128), 256, MMA_SMEM>>>(
        s.hh, s.hl, s.wqkvth, s.wqkvtl, s.bqkv, nullptr, nullptr, s.qkvh, s.qkvl, 3*D, D);
    // 4. scores (tensor) -> fp32 lower triangle
    score_mma<<<dim3(SQ/128, SQ/128, NH), 256, MMA_SMEM>>>(
        s.qkvh, s.qkvl, s.qkvh + D, s.qkvl + D, attn);
    // 5. softmax -> fp32 + split
    softmax_kernel<<<dim3(SQ, NH), blk>>>(attn, s.attnh, s.attnl);
    // 6. AV (tensor) -> ctx split
    av_mma<<<dim3(SQ/128, NH), 256, AV_SMEM>>>(
        s.attnh, s.attnl, s.qkvh, s.qkvl, s.ctxh, s.ctxl);
    // 7. mha = ctx @ Wo + bo -> split
    mma_gemm<0,1,0,0><<<dim3(D/128, SQ/128), 256, MMA_SMEM>>>(
        s.ctxh, s.ctxl, s.woth, s.wotl, bo, nullptr, nullptr, s.mhah, s.mhal, D, D);
    // 8. p1 = x + mha @ W2 + b2 -> fp32
    mma_gemm<1,0,0,1><<<dim3(D/128, SQ/128), 256, MMA_SMEM>>>(
        s.mhah, s.mhal, s.w2th, s.w2tl, b2, x, s.p1, nullptr, nullptr, D, D);
    // 9. LN2 -> fp32 + split
    ln_kernel<1,1><<<SQ, blk>>>(s.p1, g2, beta2, s.n2, s.n2h, s.n2l);
    // 10. ff1 = relu(n2 @ Wf1 + bf1) -> split
    mma_gemm<0,1,1,0><<<dim3(DFF/128, SQ/128), 256, MMA_SMEM>>>(
        s.n2h, s.n2l, s.wf1th, s.wf1tl, bf1, nullptr, nullptr, s.ff1h, s.ff1l, DFF, D);
    // 11. out = n2 + ff1 @ Wf2 + bf2 -> fp32
    mma_gemm<1,0,0,1><<<dim3(D/128, SQ/128), 256, MMA_SMEM>>>(
        s.ff1h, s.ff1l, s.wf2th, s.wf2tl, bf2, s.n2, out, nullptr, nullptr, D, DFF);
}

// round 7
// speedup vs baseline: 4.1159x; 1.0282x over previous
#include <cuda_runtime.h>
#include <cuda_bf16.h>
#include <math.h>
#include <stdint.h>

#define SQ   2048
#define D    1024
#define NH   16
#define DK   64
#define DFF  4096

// ================= PTX helpers (baseline ISA only) ==========================
__device__ __forceinline__ uint32_t smem_u32(const void* p) {
    uint32_t a;
    asm("{ .reg .u64 t; cvta.to.shared.u64 t, %1; cvt.u32.u64 %0, t; }" : "=r"(a) : "l"(p));
    return a;
}
__device__ __forceinline__ void cpa16(uint32_t dst, const void* src) {
    asm volatile("cp.async.cg.shared.global [%0], [%1], 16;" :: "r"(dst), "l"(src));
}
#define CPA_COMMIT() asm volatile("cp.async.commit_group;" ::: "memory")
__device__ __forceinline__ void ldm_x4(uint32_t& r0, uint32_t& r1, uint32_t& r2, uint32_t& r3, uint32_t addr) {
    asm volatile("ldmatrix.sync.aligned.m8n8.x4.shared.b16 {%0,%1,%2,%3}, [%4];"
                 : "=r"(r0), "=r"(r1), "=r"(r2), "=r"(r3) : "r"(addr));
}
__device__ __forceinline__ void ldm_x2(uint32_t& r0, uint32_t& r1, uint32_t addr) {
    asm volatile("ldmatrix.sync.aligned.m8n8.x2.shared.b16 {%0,%1}, [%2];"
                 : "=r"(r0), "=r"(r1) : "r"(addr));
}
__device__ __forceinline__ void ldm_x2t(uint32_t& r0, uint32_t& r1, uint32_t addr) {
    asm volatile("ldmatrix.sync.aligned.m8n8.x2.trans.shared.b16 {%0,%1}, [%2];"
                 : "=r"(r0), "=r"(r1) : "r"(addr));
}
__device__ __forceinline__ void mma_bf16(float* c, uint32_t a0, uint32_t a1, uint32_t a2, uint32_t a3,
                                         uint32_t b0, uint32_t b1) {
    asm volatile("mma.sync.aligned.m16n8k16.row.col.f32.bf16.bf16.f32 "
                 "{%0,%1,%2,%3}, {%4,%5,%6,%7}, {%8,%9}, {%0,%1,%2,%3};"
                 : "+f"(c[0]), "+f"(c[1]), "+f"(c[2]), "+f"(c[3])
                 : "r"(a0), "r"(a1), "r"(a2), "r"(a3), "r"(b0), "r"(b1));
}
__device__ __forceinline__ float wred_max(float v) {
#pragma unroll
    for (int o = 16; o > 0; o >>= 1) v = fmaxf(v, __shfl_xor_sync(0xffffffffu, v, o));
    return v;
}
__device__ __forceinline__ float wred_sum(float v) {
#pragma unroll
    for (int o = 16; o > 0; o >>= 1) v += __shfl_xor_sync(0xffffffffu, v, o);
    return v;
}

// ================= scratch =================
__device__ __nv_bfloat16 g_nx_h[SQ * D],  g_nx_l[SQ * D];
__device__ __nv_bfloat16 g_h_h[SQ * D],   g_h_l[SQ * D];
__device__ __nv_bfloat16 g_qkv_h[SQ * 3 * D], g_qkv_l[SQ * 3 * D];
__device__ __nv_bfloat16 g_ctx_h[SQ * D], g_ctx_l[SQ * D];
__device__ __nv_bfloat16 g_mha_h[SQ * D], g_mha_l[SQ * D];
__device__ float         g_p1[SQ * D];
__device__ float         g_n2[SQ * D];
__device__ __nv_bfloat16 g_n2_h[SQ * D],  g_n2_l[SQ * D];
__device__ __nv_bfloat16 g_ff1_h[SQ * DFF], g_ff1_l[SQ * DFF];
__device__ float         g_attn_scratch[(size_t)NH * SQ * SQ];
__device__ __nv_bfloat16 g_attn_h[(size_t)NH * SQ * SQ];
__device__ __nv_bfloat16 g_attn_l[(size_t)NH * SQ * SQ];
// transposed/split weights [N, K]
__device__ __nv_bfloat16 g_wint_h[D * D],      g_wint_l[D * D];
__device__ __nv_bfloat16 g_wqkvt_h[3 * D * D], g_wqkvt_l[3 * D * D];
__device__ __nv_bfloat16 g_wot_h[D * D],       g_wot_l[D * D];
__device__ __nv_bfloat16 g_w2t_h[D * D],       g_w2t_l[D * D];
__device__ __nv_bfloat16 g_wf1t_h[DFF * D],    g_wf1t_l[DFF * D];
__device__ __nv_bfloat16 g_wf2t_h[D * DFF],    g_wf2t_l[D * DFF];
__device__ float         g_bqkv[3 * D];

// ================= batched weight prep ======================================
// transpose W[K,N] fp32 -> T[N,K] bf16 hi/lo for a 32x32 tile
__device__ __forceinline__ void wprep_tile(
    const float* __restrict__ W, __nv_bfloat16* __restrict__ Th,
    __nv_bfloat16* __restrict__ Tl, int K, int N, int rowoff, int n0, int k0)
{
    __shared__ float t[32][33];
    const int tx = threadIdx.x, ty = threadIdx.y;
    for (int i = ty; i < 32; i += 8)
        t[i][tx] = W[(size_t)(k0 + i) * N + n0 + tx];
    __syncthreads();
    for (int i = ty; i < 32; i += 8) {
        float v = t[tx][i];
        __nv_bfloat16 h = __float2bfloat16_rn(v);
        size_t o = (size_t)(rowoff + n0 + i) * K + k0 + tx;
        Th[o] = h;
        Tl[o] = __float2bfloat16_rn(v - __bfloat162float(h));
    }
}

// all 6 DxD matrices, grid (32, 32, 6), block (32, 8). Also concats qkv bias.
__global__ __launch_bounds__(256) void wprep_dd(
    const float* __restrict__ W_in, const float* __restrict__ Wq,
    const float* __restrict__ Wk,   const float* __restrict__ Wv,
    const float* __restrict__ Wo,   const float* __restrict__ W2,
    const float* __restrict__ bq,   const float* __restrict__ bk,
    const float* __restrict__ bv,
    __nv_bfloat16* winth, __nv_bfloat16* wintl,
    __nv_bfloat16* wqkvth, __nv_bfloat16* wqkvtl,
    __nv_bfloat16* woth, __nv_bfloat16* wotl,
    __nv_bfloat16* w2th, __nv_bfloat16* w2tl, float* bqkv)
{
    const int z = blockIdx.z;
    const float* W; __nv_bfloat16 *Th, *Tl; int rowoff = 0;
    switch (z) {
        case 0:  W = W_in; Th = winth;  Tl = wintl;  break;
        case 1:  W = Wq;   Th = wqkvth; Tl = wqkvtl; rowoff = 0;     break;
        case 2:  W = Wk;   Th = wqkvth; Tl = wqkvtl; rowoff = D;     break;
        case 3:  W = Wv;   Th = wqkvth; Tl = wqkvtl; rowoff = 2 * D; break;
        case 4:  W = Wo;   Th = woth;   Tl = wotl;   break;
        default: W = W2;   Th = w2th;   Tl = w2tl;   break;
    }
    wprep_tile(W, Th, Tl, D, D, rowoff, blockIdx.x * 32, blockIdx.y * 32);
    if (z >= 1 && z <= 3 && blockIdx.x == 0 && blockIdx.y == 0) {
        const float* b = (z == 1) ? bq : (z == 2) ? bk : bv;
        for (int j = threadIdx.y * 32 + threadIdx.x; j < D; j += 256)
            bqkv[(z - 1) * D + j] = b[j];
    }
}

// Wf1 [D,DFF] and Wf2 [DFF,D], grid (128, 32, 2), block (32, 8)
__global__ __launch_bounds__(256) void wprep_ff(
    const float* __restrict__ Wf1, const float* __restrict__ Wf2,
    __nv_bfloat16* f1h, __nv_bfloat16* f1l,
    __nv_bfloat16* f2h, __nv_bfloat16* f2l)
{
    const int z = blockIdx.z;
    if (z == 0)
        wprep_tile(Wf1, f1h, f1l, D, DFF, 0, blockIdx.x * 32, blockIdx.y * 32);
    else
        wprep_tile(Wf2, f2h, f2l, DFF, D, 0, blockIdx.y * 32, blockIdx.x * 32);
}

// ================= LayerNorm (warp-shuffle reductions) ======================
template<int WF32, int WSPLIT>
__global__ __launch_bounds__(256) void ln_kernel(
    const float* __restrict__ x, const float* __restrict__ g,
    const float* __restrict__ b, float* __restrict__ outf,
    __nv_bfloat16* __restrict__ oh, __nv_bfloat16* __restrict__ ol)
{
    __shared__ float red[8];
    __shared__ float bc[2];
    const int row = blockIdx.x;
    const int tid = threadIdx.x;
    const int lane = tid & 31, warp = tid >> 5;
    float4 v = *(const float4*)(x + (size_t)row * D + tid * 4);

    float s = wred_sum(v.x + v.y + v.z + v.w);
    if (lane == 0) red[warp] = s;
    __syncthreads();
    if (warp == 0) {
        float t = red[lane & 7];
        t += __shfl_xor_sync(0xffffffffu, t, 1);
        t += __shfl_xor_sync(0xffffffffu, t, 2);
        t += __shfl_xor_sync(0xffffffffu, t, 4);
        if (lane == 0) bc[0] = t;
    }
    __syncthreads();
    const float mean = bc[0] * (1.0f / D);
    const float dx = v.x - mean, dy = v.y - mean, dz = v.z - mean, dw = v.w - mean;

    float s2 = wred_sum(dx * dx + dy * dy + dz * dz + dw * dw);
    if (lane == 0) red[warp] = s2;
    __syncthreads();
    if (warp == 0) {
        float t = red[lane & 7];
        t += __shfl_xor_sync(0xffffffffu, t, 1);
        t += __shfl_xor_sync(0xffffffffu, t, 2);
        t += __shfl_xor_sync(0xffffffffu, t, 4);
        if (lane == 0) bc[1] = t;
    }
    __syncthreads();
    const float inv = 1.0f / (sqrtf(bc[1] * (1.0f / D)) + 1e-6f);

    float4 gg = *(const float4*)(g + tid * 4);
    float4 bb = *(const float4*)(b + tid * 4);
    float o0 = gg.x * dx * inv + bb.x;
    float o1 = gg.y * dy * inv + bb.y;
    float o2 = gg.z * dz * inv + bb.z;
    float o3 = gg.w * dw * inv + bb.w;
    const size_t base = (size_t)row * D + tid * 4;
    if (WF32) {
        float4 o4 = {o0, o1, o2, o3};
        *(float4*)(outf + base) = o4;
    }
    if (WSPLIT) {
        float vv[4] = {o0, o1, o2, o3};
        __nv_bfloat16 hs[4], ls[4];
#pragma unroll
        for (int i = 0; i < 4; i++) {
            hs[i] = __float2bfloat16_rn(vv[i]);
            ls[i] = __float2bfloat16_rn(vv[i] - __bfloat162float(hs[i]));
        }
        *(uint2*)(oh + base) = *(uint2*)hs;
        *(uint2*)(ol + base) = *(uint2*)ls;
    }
}

// ================= shared GEMM plumbing ======================================
#define STG_A_H 0
#define STG_A_L 8192
#define STG_B_H 16384
#define STG_B_L 24576
#define STG_SZ  32768
#define MMA_SMEM (3 * STG_SZ)
#define SCORE_SMEM (2 * STG_SZ)

__device__ __forceinline__ uint32_t swz(int row, int kb) {
    return (uint32_t)(row * 64 + ((kb ^ ((row >> 1) & 3)) << 4));
}

__device__ __forceinline__ void load_tile(
    const __nv_bfloat16* __restrict__ g, int ld, int row0, int k0, uint32_t sbase, int tid)
{
#pragma unroll
    for (int it = 0; it < 2; it++) {
        int c = tid + (it << 8);
        int row = c >> 2, kb = c & 3;
        cpa16(sbase + swz(row, kb), g + (size_t)(row0 + row) * ld + k0 + kb * 8);
    }
}

#define WAIT_REM(rem) do { \
    if ((rem) >= 2)      asm volatile("cp.async.wait_group 2;" ::: "memory"); \
    else if ((rem) == 1) asm volatile("cp.async.wait_group 1;" ::: "memory"); \
    else                 asm volatile("cp.async.wait_group 0;" ::: "memory"); \
} while (0)

// ================= mma.sync GEMM (3-stage): C[M,N] = A[M,K] @ T[N,K]^T =======
template<int WF32, int WSPLIT, int RELU, int RESID>
__global__ __launch_bounds__(256, 1) void mma_gemm(
    const __nv_bfloat16* __restrict__ Ah, const __nv_bfloat16* __restrict__ Al,
    const __nv_bfloat16* __restrict__ Bh, const __nv_bfloat16* __restrict__ Bl,
    const float* __restrict__ bias, const float* __restrict__ res,
    float* __restrict__ Cf, __nv_bfloat16* __restrict__ Chi, __nv_bfloat16* __restrict__ Clo,
    int N, int K)
{
    extern __shared__ char smem[];
    const uint32_t sb = smem_u32(smem);
    const int tid = threadIdx.x, wid = tid >> 5, lane = tid & 31;
    const int warp_m = wid & 1;
    const int warp_n = wid >> 1;
    const int brow = blockIdx.y * 128, bcol = blockIdx.x * 128;

    float acc[4][4][4];
#pragma unroll
    for (int a = 0; a < 4; a++)
#pragma unroll
        for (int b = 0; b < 4; b++)
#pragma unroll
            for (int c = 0; c < 4; c++) acc[a][b][c] = 0.0f;

    const int nch = K >> 5;
    {
        load_tile(Ah, K, brow, 0, sb + STG_A_H, tid);
        load_tile(Al, K, brow, 0, sb + STG_A_L, tid);
        load_tile(Bh, K, bcol, 0, sb + STG_B_H, tid);
        load_tile(Bl, K, bcol, 0, sb + STG_B_L, tid);
        CPA_COMMIT();
    }
    if (nch > 1) {
        const uint32_t st = sb + STG_SZ;
        load_tile(Ah, K, brow, 32, st + STG_A_H, tid);
        load_tile(Al, K, brow, 32, st + STG_A_L, tid);
        load_tile(Bh, K, bcol, 32, st + STG_B_H, tid);
        load_tile(Bl, K, bcol, 32, st + STG_B_L, tid);
        CPA_COMMIT();
    }

    const int tileA = lane >> 3;
    const int rinA  = (lane & 7) + ((tileA & 1) << 3);
    const int kbA   = tileA >> 1;
    const int i16   = lane & 15;
    const int rinB  = i16 & 7;
    const int kbB   = i16 >> 3;

    for (int i = 0; i < nch; i++) {
        if (i + 2 < nch) {
            const uint32_t st = sb + ((i + 2) % 3) * STG_SZ;
            const int k0 = (i + 2) << 5;
            load_tile(Ah, K, brow, k0, st + STG_A_H, tid);
            load_tile(Al, K, brow, k0, st + STG_A_L, tid);
            load_tile(Bh, K, bcol, k0, st + STG_B_H, tid);
            load_tile(Bl, K, bcol, k0, st + STG_B_L, tid);
            CPA_COMMIT();
        }
        WAIT_REM(nch - 1 - i);
        __syncthreads();

        const uint32_t st = sb + (i % 3) * STG_SZ;
#pragma unroll
        for (int ks = 0; ks < 2; ks++) {
            uint32_t bh[4][2], bl[4][2];
#pragma unroll
            for (int nt = 0; nt < 4; nt++) {
                const int rowb = warp_n * 32 + nt * 8 + rinB;
                const uint32_t off = swz(rowb, (ks << 1) + kbB);
                ldm_x2(bh[nt][0], bh[nt][1], st + STG_B_H + off);
                ldm_x2(bl[nt][0], bl[nt][1], st + STG_B_L + off);
            }
#pragma unroll
            for (int mt = 0; mt < 4; mt++) {
                const int rowa = warp_m * 64 + mt * 16 + rinA;
                const uint32_t off = swz(rowa, (ks << 1) + kbA);
                uint32_t a0, a1, a2, a3, l0, l1, l2, l3;
                ldm_x4(a0, a1, a2, a3, st + STG_A_H + off);
                ldm_x4(l0, l1, l2, l3, st + STG_A_L + off);
#pragma unroll
                for (int nt = 0; nt < 4; nt++) {
                    mma_bf16(acc[mt][nt], a0, a1, a2, a3, bh[nt][0], bh[nt][1]);
                    mma_bf16(acc[mt][nt], a0, a1, a2, a3, bl[nt][0], bl[nt][1]);
                    mma_bf16(acc[mt][nt], l0, l1, l2, l3, bh[nt][0], bh[nt][1]);
                }
            }
        }
        __syncthreads();
    }

    const int g4 = lane >> 2, t4 = lane & 3;
#pragma unroll
    for (int mt = 0; mt < 4; mt++) {
#pragma unroll
        for (int half = 0; half < 2; half++) {
            const int row = brow + warp_m * 64 + mt * 16 + g4 + half * 8;
#pragma unroll
            for (int nt = 0; nt < 4; nt++) {
                const int col = bcol + warp_n * 32 + nt * 8 + t4 * 2;
                float v0 = acc[mt][nt][half * 2 + 0] + bias[col];
                float v1 = acc[mt][nt][half * 2 + 1] + bias[col + 1];
                if (RELU) { v0 = fmaxf(v0, 0.0f); v1 = fmaxf(v1, 0.0f); }
                const size_t o = (size_t)row * N + col;
                if (RESID) { v0 += res[o]; v1 += res[o + 1]; }
                if (WF32) {
                    float2 f2 = {v0, v1};
                    *(float2*)(Cf + o) = f2;
                }
                if (WSPLIT) {
                    __nv_bfloat16 h0 = __float2bfloat16_rn(v0);
                    __nv_bfloat16 h1 = __float2bfloat16_rn(v1);
                    __nv_bfloat16 q0 = __float2bfloat16_rn(v0 - __bfloat162float(h0));
                    __nv_bfloat16 q1 = __float2bfloat16_rn(v1 - __bfloat162float(h1));
                    __nv_bfloat162 hp = {h0, h1}, lp = {q0, q1};
                    *(__nv_bfloat162*)(Chi + o) = hp;
                    *(__nv_bfloat162*)(Clo + o) = lp;
                }
            }
        }
    }
}

// ================= score mma: S = (Q K^T)/8, causal ==========================
__global__ __launch_bounds__(256, 1) void score_mma(
    const __nv_bfloat16* __restrict__ qh, const __nv_bfloat16* __restrict__ ql,
    const __nv_bfloat16* __restrict__ kh, const __nv_bfloat16* __restrict__ kl,
    float* __restrict__ attn)
{
    const int brow = blockIdx.y * 128, bcol = blockIdx.x * 128;
    if (bcol >= brow + 128) return;
    const int h = blockIdx.z;
    const __nv_bfloat16* Ah = qh + h * DK;
    const __nv_bfloat16* Al = ql + h * DK;
    const __nv_bfloat16* Bh = kh + h * DK;
    const __nv_bfloat16* Bl = kl + h * DK;

    extern __shared__ char smem[];
    const uint32_t sb = smem_u32(smem);
    const int tid = threadIdx.x, wid = tid >> 5, lane = tid & 31;
    const int warp_m = wid & 1, warp_n = wid >> 1;

    float acc[4][4][4];
#pragma unroll
    for (int a = 0; a < 4; a++)
#pragma unroll
        for (int b = 0; b < 4; b++)
#pragma unroll
            for (int c = 0; c < 4; c++) acc[a][b][c] = 0.0f;

    load_tile(Ah, 3 * D, brow, 0, sb + STG_A_H, tid);
    load_tile(Al, 3 * D, brow, 0, sb + STG_A_L, tid);
    load_tile(Bh, 3 * D, bcol, 0, sb + STG_B_H, tid);
    load_tile(Bl, 3 * D, bcol, 0, sb + STG_B_L, tid);
    CPA_COMMIT();

    const int tileA = lane >> 3;
    const int rinA  = (lane & 7) + ((tileA & 1) << 3);
    const int kbA   = tileA >> 1;
    const int i16   = lane & 15;
    const int rinB  = i16 & 7;
    const int kbB   = i16 >> 3;

    for (int i = 0; i < 2; i++) {
        if (i == 0) {
            const uint32_t st = sb + STG_SZ;
            load_tile(Ah, 3 * D, brow, 32, st + STG_A_H, tid);
            load_tile(Al, 3 * D, brow, 32, st + STG_A_L, tid);
            load_tile(Bh, 3 * D, bcol, 32, st + STG_B_H, tid);
            load_tile(Bl, 3 * D, bcol, 32, st + STG_B_L, tid);
            CPA_COMMIT();
            asm volatile("cp.async.wait_group 1;" ::: "memory");
        } else {
            asm volatile("cp.async.wait_group 0;" ::: "memory");
        }
        __syncthreads();

        const uint32_t st = sb + (i & 1) * STG_SZ;
#pragma unroll
        for (int ks = 0; ks < 2; ks++) {
            uint32_t bh[4][2], bl[4][2];
#pragma unroll
            for (int nt = 0; nt < 4; nt++) {
                const int rowb = warp_n * 32 + nt * 8 + rinB;
                const uint32_t off = swz(rowb, (ks << 1) + kbB);
                ldm_x2(bh[nt][0], bh[nt][1], st + STG_B_H + off);
                ldm_x2(bl[nt][0], bl[nt][1], st + STG_B_L + off);
            }
#pragma unroll
            for (int mt = 0; mt < 4; mt++) {
                const int rowa = warp_m * 64 + mt * 16 + rinA;
                const uint32_t off = swz(rowa, (ks << 1) + kbA);
                uint32_t a0, a1, a2, a3, l0, l1, l2, l3;
                ldm_x4(a0, a1, a2, a3, st + STG_A_H + off);
                ldm_x4(l0, l1, l2, l3, st + STG_A_L + off);
#pragma unroll
                for (int nt = 0; nt < 4; nt++) {
                    mma_bf16(acc[mt][nt], a0, a1, a2, a3, bh[nt][0], bh[nt][1]);
                    mma_bf16(acc[mt][nt], a0, a1, a2, a3, bl[nt][0], bl[nt][1]);
                    mma_bf16(acc[mt][nt], l0, l1, l2, l3, bh[nt][0], bh[nt][1]);
                }
            }
        }
        __syncthreads();
    }

    const int g4 = lane >> 2, t4 = lane & 3;
#pragma unroll
    for (int mt = 0; mt < 4; mt++) {
#pragma unroll
        for (int half = 0; half < 2; half++) {
            const int row = brow + warp_m * 64 + mt * 16 + g4 + half * 8;
            float* arow = attn + ((size_t)h * SQ + row) * SQ;
#pragma unroll
            for (int nt = 0; nt < 4; nt++) {
                const int col = bcol + warp_n * 32 + nt * 8 + t4 * 2;
                if (col <= row)     arow[col]     = acc[mt][nt][half * 2 + 0] * 0.125f;
                if (col + 1 <= row) arow[col + 1] = acc[mt][nt][half * 2 + 1] * 0.125f;
            }
        }
    }
}

// ================= softmax (warp-shuffle): fp32 out + bf16 hi/lo =============
__global__ __launch_bounds__(256) void softmax_kernel(
    float* __restrict__ attn,
    __nv_bfloat16* __restrict__ ah, __nv_bfloat16* __restrict__ al)
{
    __shared__ float p[SQ];
    __shared__ float red[8];
    __shared__ float bc[2];
    const int i   = blockIdx.x;
    const int h   = blockIdx.y;
    const int tid = threadIdx.x;
    const int lane = tid & 31, warp = tid >> 5;
    const size_t rb = ((size_t)h * SQ + i) * SQ;
    float* row = attn + rb;

    float m = -INFINITY;
    for (int j = tid; j <= i; j += 256) { float s = row[j]; p[j] = s; m = fmaxf(m, s); }
    m = wred_max(m);
    if (lane == 0) red[warp] = m;
    __syncthreads();
    if (warp == 0) {
        float t = red[lane & 7];
        t = fmaxf(t, __shfl_xor_sync(0xffffffffu, t, 1));
        t = fmaxf(t, __shfl_xor_sync(0xffffffffu, t, 2));
        t = fmaxf(t, __shfl_xor_sync(0xffffffffu, t, 4));
        if (lane == 0) bc[0] = t;
    }
    __syncthreads();
    const float mx = bc[0];

    float sum = 0.0f;
    for (int j = tid; j <= i; j += 256) { float e = __expf(p[j] - mx); p[j] = e; sum += e; }
    sum = wred_sum(sum);
    __syncthreads();           // red[] reuse safety
    if (lane == 0) red[warp] = sum;
    __syncthreads();
    if (warp == 0) {
        float t = red[lane & 7];
        t += __shfl_xor_sync(0xffffffffu, t, 1);
        t += __shfl_xor_sync(0xffffffffu, t, 2);
        t += __shfl_xor_sync(0xffffffffu, t, 4);
        if (lane == 0) bc[1] = t;
    }
    __syncthreads();
    const float inv = 1.0f / bc[1];

    const int lim = ((i >> 7) + 1) << 7;   // AV never reads past this
    for (int j = tid; j <= i; j += 256) {
        float w = p[j] * inv;
        row[j] = w;
        __nv_bfloat16 hh = __float2bfloat16_rn(w);
        ah[rb + j] = hh;
        al[rb + j] = __float2bfloat16_rn(w - __bfloat162float(hh));
    }
    for (int j = i + 1 + tid; j < SQ; j += 256) row[j] = 0.0f;
    const __nv_bfloat16 z = __float2bfloat16_rn(0.0f);
    for (int j = i + 1 + tid; j < lim; j += 256) { ah[rb + j] = z; al[rb + j] = z; }
}

// ================= AV mma (3-stage): ctx = P @ V =============================
#define AV_A_H 0
#define AV_A_L 8192
#define AV_B_H 16384
#define AV_B_L 20480
#define AV_STG 24576
#define AV_SMEM (3 * AV_STG)

__global__ __launch_bounds__(256, 1) void av_mma(
    const __nv_bfloat16* __restrict__ ah, const __nv_bfloat16* __restrict__ al,
    const __nv_bfloat16* __restrict__ vh, const __nv_bfloat16* __restrict__ vl,
    __nv_bfloat16* __restrict__ ch, __nv_bfloat16* __restrict__ cl)
{
    const int brow = blockIdx.x * 128;
    const int h    = blockIdx.y;
    const __nv_bfloat16* Ah = ah + (size_t)h * SQ * SQ;
    const __nv_bfloat16* Al = al + (size_t)h * SQ * SQ;
    const __nv_bfloat16* Vh = vh + 2 * D + h * DK;
    const __nv_bfloat16* Vl = vl + 2 * D + h * DK;

    extern __shared__ char smem[];
    const uint32_t sb = smem_u32(smem);
    const int tid = threadIdx.x, wid = tid >> 5, lane = tid & 31;
    const int warp_m = wid & 3;
    const int warp_n = wid >> 2;

    float acc[2][4][4];
#pragma unroll
    for (int a = 0; a < 2; a++)
#pragma unroll
        for (int b = 0; b < 4; b++)
#pragma unroll
            for (int c = 0; c < 4; c++) acc[a][b][c] = 0.0f;

    auto load_b = [&](const __nv_bfloat16* V, int k0, uint32_t sbase) {
        int r = tid >> 3, g = tid & 7;
        cpa16(sbase + (uint32_t)(r * 128 + ((g ^ (r & 7)) << 4)),
              V + (size_t)(k0 + r) * (3 * D) + g * 8);
    };
    auto load_stage = [&](int ci, uint32_t st) {
        const int k0 = ci << 5;
        load_tile(Ah, SQ, brow, k0, st + AV_A_H, tid);
        load_tile(Al, SQ, brow, k0, st + AV_A_L, tid);
        load_b(Vh, k0, st + AV_B_H);
        load_b(Vl, k0, st + AV_B_L);
        CPA_COMMIT();
    };

    const int nch = (brow >> 5) + 4;
    load_stage(0, sb);
    if (nch > 1) load_stage(1, sb + AV_STG);

    const int tileA = lane >> 3;
    const int rinA  = (lane & 7) + ((tileA & 1) << 3);
    const int kbA   = tileA >> 1;
    const int i16   = lane & 15;

    for (int i = 0; i < nch; i++) {
        if (i + 2 < nch) load_stage(i + 2, sb + ((i + 2) % 3) * AV_STG);
        WAIT_REM(nch - 1 - i);
        __syncthreads();

        const uint32_t st = sb + (i % 3) * AV_STG;
#pragma unroll
        for (int ks = 0; ks < 2; ks++) {
            uint32_t bh[4][2], bl[4][2];
#pragma unroll
            for (int nt = 0; nt < 4; nt++) {
                const int krow = ks * 16 + i16;
                const int gB = warp_n * 4 + nt;
                const uint32_t off = (uint32_t)(krow * 128 + ((gB ^ (krow & 7)) << 4));
                ldm_x2t(bh[nt][0], bh[nt][1], st + AV_B_H + off);
                ldm_x2t(bl[nt][0], bl[nt][1], st + AV_B_L + off);
            }
#pragma unroll
            for (int mt = 0; mt < 2; mt++) {
                const int rowa = warp_m * 32 + mt * 16 + rinA;
                const uint32_t off = swz(rowa, (ks << 1) + kbA);
                uint32_t a0, a1, a2, a3, l0, l1, l2, l3;
                ldm_x4(a0, a1, a2, a3, st + AV_A_H + off);
                ldm_x4(l0, l1, l2, l3, st + AV_A_L + off);
#pragma unroll
                for (int nt = 0; nt < 4; nt++) {
                    mma_bf16(acc[mt][nt], a0, a1, a2, a3, bh[nt][0], bh[nt][1]);
                    mma_bf16(acc[mt][nt], a0, a1, a2, a3, bl[nt][0], bl[nt][1]);
                    mma_bf16(acc[mt][nt], l0, l1, l2, l3, bh[nt][0], bh[nt][1]);
                }
            }
        }
        __syncthreads();
    }

    const int g4 = lane >> 2, t4 = lane & 3;
#pragma unroll
    for (int mt = 0; mt < 2; mt++) {
#pragma unroll
        for (int half = 0; half < 2; half++) {
            const int row = brow + warp_m * 32 + mt * 16 + g4 + half * 8;
#pragma unroll
            for (int nt = 0; nt < 4; nt++) {
                const int col = h * DK + warp_n * 32 + nt * 8 + t4 * 2;
                float v0 = acc[mt][nt][half * 2 + 0];
                float v1 = acc[mt][nt][half * 2 + 1];
                const size_t o = (size_t)row * D + col;
                __nv_bfloat16 h0 = __float2bfloat16_rn(v0);
                __nv_bfloat16 h1 = __float2bfloat16_rn(v1);
                __nv_bfloat16 q0 = __float2bfloat16_rn(v0 - __bfloat162float(h0));
                __nv_bfloat16 q1 = __float2bfloat16_rn(v1 - __bfloat162float(h1));
                __nv_bfloat162 hp = {h0, h1}, lp = {q0, q1};
                *(__nv_bfloat162*)(ch + o) = hp;
                *(__nv_bfloat162*)(cl + o) = lp;
            }
        }
    }
}

// ================= host driver =================
struct Scratch {
    __nv_bfloat16 *nxh, *nxl, *hh, *hl, *qkvh, *qkvl, *ctxh, *ctxl, *mhah, *mhal, *n2h, *n2l, *ff1h, *ff1l;
    __nv_bfloat16 *attnh, *attnl;
    __nv_bfloat16 *winth, *wintl, *wqkvth, *wqkvtl, *woth, *wotl, *w2th, *w2tl, *wf1th, *wf1tl, *wf2th, *wf2tl;
    float *p1, *n2, *attn, *bqkv;
};

static Scratch get_scratch() {
    static Scratch s = [] {
        Scratch t;
        void* p;
        cudaGetSymbolAddress(&p, g_nx_h);   t.nxh = (__nv_bfloat16*)p;
        cudaGetSymbolAddress(&p, g_nx_l);   t.nxl = (__nv_bfloat16*)p;
        cudaGetSymbolAddress(&p, g_h_h);    t.hh  = (__nv_bfloat16*)p;
        cudaGetSymbolAddress(&p, g_h_l);    t.hl  = (__nv_bfloat16*)p;
        cudaGetSymbolAddress(&p, g_qkv_h);  t.qkvh = (__nv_bfloat16*)p;
        cudaGetSymbolAddress(&p, g_qkv_l);  t.qkvl = (__nv_bfloat16*)p;
        cudaGetSymbolAddress(&p, g_ctx_h);  t.ctxh = (__nv_bfloat16*)p;
        cudaGetSymbolAddress(&p, g_ctx_l);  t.ctxl = (__nv_bfloat16*)p;
        cudaGetSymbolAddress(&p, g_mha_h);  t.mhah = (__nv_bfloat16*)p;
        cudaGetSymbolAddress(&p, g_mha_l);  t.mhal = (__nv_bfloat16*)p;
        cudaGetSymbolAddress(&p, g_n2_h);   t.n2h = (__nv_bfloat16*)p;
        cudaGetSymbolAddress(&p, g_n2_l);   t.n2l = (__nv_bfloat16*)p;
        cudaGetSymbolAddress(&p, g_ff1_h);  t.ff1h = (__nv_bfloat16*)p;
        cudaGetSymbolAddress(&p, g_ff1_l);  t.ff1l = (__nv_bfloat16*)p;
        cudaGetSymbolAddress(&p, g_attn_h); t.attnh = (__nv_bfloat16*)p;
        cudaGetSymbolAddress(&p, g_attn_l); t.attnl = (__nv_bfloat16*)p;
        cudaGetSymbolAddress(&p, g_wint_h); t.winth = (__nv_bfloat16*)p;
        cudaGetSymbolAddress(&p, g_wint_l); t.wintl = (__nv_bfloat16*)p;
        cudaGetSymbolAddress(&p, g_wqkvt_h); t.wqkvth = (__nv_bfloat16*)p;
        cudaGetSymbolAddress(&p, g_wqkvt_l); t.wqkvtl = (__nv_bfloat16*)p;
        cudaGetSymbolAddress(&p, g_wot_h);  t.woth = (__nv_bfloat16*)p;
        cudaGetSymbolAddress(&p, g_wot_l);  t.wotl = (__nv_bfloat16*)p;
        cudaGetSymbolAddress(&p, g_w2t_h);  t.w2th = (__nv_bfloat16*)p;
        cudaGetSymbolAddress(&p, g_w2t_l);  t.w2tl = (__nv_bfloat16*)p;
        cudaGetSymbolAddress(&p, g_wf1t_h); t.wf1th = (__nv_bfloat16*)p;
        cudaGetSymbolAddress(&p, g_wf1t_l); t.wf1tl = (__nv_bfloat16*)p;
        cudaGetSymbolAddress(&p, g_wf2t_h); t.wf2th = (__nv_bfloat16*)p;
        cudaGetSymbolAddress(&p, g_wf2t_l); t.wf2tl = (__nv_bfloat16*)p;
        cudaGetSymbolAddress(&p, g_p1);     t.p1  = (float*)p;
        cudaGetSymbolAddress(&p, g_n2);     t.n2  = (float*)p;
        cudaGetSymbolAddress(&p, g_attn_scratch); t.attn = (float*)p;
        cudaGetSymbolAddress(&p, g_bqkv);   t.bqkv = (float*)p;
        cudaFuncSetAttribute((const void*)mma_gemm<0,1,0,0>, cudaFuncAttributeMaxDynamicSharedMemorySize, MMA_SMEM);
        cudaFuncSetAttribute((const void*)mma_gemm<1,0,0,1>, cudaFuncAttributeMaxDynamicSharedMemorySize, MMA_SMEM);
        cudaFuncSetAttribute((const void*)mma_gemm<0,1,1,0>, cudaFuncAttributeMaxDynamicSharedMemorySize, MMA_SMEM);
        cudaFuncSetAttribute((const void*)score_mma, cudaFuncAttributeMaxDynamicSharedMemorySize, SCORE_SMEM);
        cudaFuncSetAttribute((const void*)av_mma,    cudaFuncAttributeMaxDynamicSharedMemorySize, AV_SMEM);
        return t;
    }();
    return s;
}

extern "C" void kernel_launch(void* const* d_in, const int* in_sizes, int n_in,
                              void* d_out, int out_size)
{
    const float* x     = (const float*)d_in[0];
    const float* g1    = (const float*)d_in[1];
    const float* beta1 = (const float*)d_in[2];
    const float* W_in  = (const float*)d_in[3];
    const float* b_in  = (const float*)d_in[4];
    const float* Wq    = (const float*)d_in[5];
    const float* bq    = (const float*)d_in[6];
    const float* Wk    = (const float*)d_in[7];
    const float* bk    = (const float*)d_in[8];
    const float* Wv    = (const float*)d_in[9];
    const float* bv    = (const float*)d_in[10];
    const float* Wo    = (const float*)d_in[11];
    const float* bo    = (const float*)d_in[12];
    const float* W2    = (const float*)d_in[13];
    const float* b2    = (const float*)d_in[14];
    const float* g2    = (const float*)d_in[15];
    const float* beta2 = (const float*)d_in[16];
    const float* Wf1   = (const float*)d_in[17];
    const float* bf1   = (const float*)d_in[18];
    const float* Wf2   = (const float*)d_in[19];
    const float* bf2   = (const float*)d_in[20];

    Scratch s = get_scratch();

    float* out  = (float*)d_out;
    const long long full = (long long)SQ * D + (long long)NH * SQ * SQ;
    float* attn = ((long long)out_size >= full) ? (out + (size_t)SQ * D) : s.attn;

    dim3 blk(256);
    dim3 wblk(32, 8);

    // #1/#2: batched weight prep (also concats qkv bias)
    wprep_dd<<<dim3(32, 32, 6), wblk>>>(
        W_in, Wq, Wk, Wv, Wo, W2, bq, bk, bv,
        s.winth, s.wintl, s.wqkvth, s.wqkvtl, s.woth, s.wotl, s.w2th, s.w2tl, s.bqkv);
    wprep_ff<<<dim3(128, 32, 2), wblk>>>(Wf1, Wf2, s.wf1th, s.wf1tl, s.wf2th, s.wf2tl);

    // #3: LN1 -> split
    ln_kernel<0,1><<<SQ, blk>>>(x, g1, beta1, nullptr, s.nxh, s.nxl);
    // #4: h = nx @ W_in + b_in -> split
    mma_gemm<0,1,0,0><<<dim3(D/128, SQ/128), 256, MMA_SMEM>>>(
        s.nxh, s.nxl, s.winth, s.wintl, b_in, nullptr, nullptr, s.hh, s.hl, D, D);
    // #5: qkv (packed N=3072) -> split
    mma_gemm<0,1,0,0><<<dim3(3*D/128, SQ/128), 256, MMA_SMEM>>>(
        s.hh, s.hl, s.wqkvth, s.wqkvtl, s.bqkv, nullptr, nullptr, s.qkvh, s.qkvl, 3*D, D);
    // #6: scores (tensor) -> fp32 lower triangle   [ncu -s 5 captures this]
    score_mma<<<dim3(SQ/128, SQ/128, NH), 256, SCORE_SMEM>>>(
        s.qkvh, s.qkvl, s.qkvh + D, s.qkvl + D, attn);
    // #7: softmax -> fp32 + split
    softmax_kernel<<<dim3(SQ, NH), blk>>>(attn, s.attnh, s.attnl);
    // #8: AV (tensor) -> ctx split
    av_mma<<<dim3(SQ/128, NH), 256, AV_SMEM>>>(
        s.attnh, s.attnl, s.qkvh, s.qkvl, s.ctxh, s.ctxl);
    // #9: mha = ctx @ Wo + bo -> split
    mma_gemm<0,1,0,0><<<dim3(D/128, SQ/128), 256, MMA_SMEM>>>(
        s.ctxh, s.ctxl, s.woth, s.wotl, bo, nullptr, nullptr, s.mhah, s.mhal, D, D);
    // #10: p1 = x + mha @ W2 + b2 -> fp32
    mma_gemm<1,0,0,1><<<dim3(D/128, SQ/128), 256, MMA_SMEM>>>(
        s.mhah, s.mhal, s.w2th, s.w2tl, b2, x, s.p1, nullptr, nullptr, D, D);
    // #11: LN2 -> fp32 + split
    ln_kernel<1,1><<<SQ, blk>>>(s.p1, g2, beta2, s.n2, s.n2h, s.n2l);
    // #12: ff1 = relu(n2 @ Wf1 + bf1) -> split
    mma_gemm<0,1,1,0><<<dim3(DFF/128, SQ/128), 256, MMA_SMEM>>>(
        s.n2h, s.n2l, s.wf1th, s.wf1tl, bf1, nullptr, nullptr, s.ff1h, s.ff1l, DFF, D);
    // #13: out = n2 + ff1 @ Wf2 + bf2 -> fp32
    mma_gemm<1,0,0,1><<<dim3(D/128, SQ/128), 256, MMA_SMEM>>>(
        s.ff1h, s.ff1l, s.wf2th, s.wf2tl, bf2, s.n2, out, nullptr, nullptr, D, DFF);
}

// round 9
// speedup vs baseline: 4.4330x; 1.0771x over previous
#include <cuda_runtime.h>
#include <cuda_bf16.h>
#include <math.h>
#include <stdint.h>

#define SQ   2048
#define D    1024
#define NH   16
#define DK   64
#define DFF  4096

// ================= PTX helpers (baseline ISA only) ==========================
__device__ __forceinline__ uint32_t smem_u32(const void* p) {
    uint32_t a;
    asm("{ .reg .u64 t; cvta.to.shared.u64 t, %1; cvt.u32.u64 %0, t; }" : "=r"(a) : "l"(p));
    return a;
}
__device__ __forceinline__ void cpa16(uint32_t dst, const void* src) {
    asm volatile("cp.async.cg.shared.global [%0], [%1], 16;" :: "r"(dst), "l"(src));
}
#define CPA_COMMIT() asm volatile("cp.async.commit_group;" ::: "memory")
__device__ __forceinline__ void ldm_x4(uint32_t& r0, uint32_t& r1, uint32_t& r2, uint32_t& r3, uint32_t addr) {
    asm volatile("ldmatrix.sync.aligned.m8n8.x4.shared.b16 {%0,%1,%2,%3}, [%4];"
                 : "=r"(r0), "=r"(r1), "=r"(r2), "=r"(r3) : "r"(addr));
}
__device__ __forceinline__ void ldm_x2(uint32_t& r0, uint32_t& r1, uint32_t addr) {
    asm volatile("ldmatrix.sync.aligned.m8n8.x2.shared.b16 {%0,%1}, [%2];"
                 : "=r"(r0), "=r"(r1) : "r"(addr));
}
__device__ __forceinline__ void ldm_x2t(uint32_t& r0, uint32_t& r1, uint32_t addr) {
    asm volatile("ldmatrix.sync.aligned.m8n8.x2.trans.shared.b16 {%0,%1}, [%2];"
                 : "=r"(r0), "=r"(r1) : "r"(addr));
}
__device__ __forceinline__ void mma_bf16(float* c, uint32_t a0, uint32_t a1, uint32_t a2, uint32_t a3,
                                         uint32_t b0, uint32_t b1) {
    asm volatile("mma.sync.aligned.m16n8k16.row.col.f32.bf16.bf16.f32 "
                 "{%0,%1,%2,%3}, {%4,%5,%6,%7}, {%8,%9}, {%0,%1,%2,%3};"
                 : "+f"(c[0]), "+f"(c[1]), "+f"(c[2]), "+f"(c[3])
                 : "r"(a0), "r"(a1), "r"(a2), "r"(a3), "r"(b0), "r"(b1));
}
__device__ __forceinline__ float wred_max(float v) {
#pragma unroll
    for (int o = 16; o > 0; o >>= 1) v = fmaxf(v, __shfl_xor_sync(0xffffffffu, v, o));
    return v;
}
__device__ __forceinline__ float wred_sum(float v) {
#pragma unroll
    for (int o = 16; o > 0; o >>= 1) v += __shfl_xor_sync(0xffffffffu, v, o);
    return v;
}

// ================= scratch =================
__device__ __nv_bfloat16 g_nx_h[SQ * D],  g_nx_l[SQ * D];
__device__ __nv_bfloat16 g_h_h[SQ * D],   g_h_l[SQ * D];
__device__ __nv_bfloat16 g_qkv_h[SQ * 3 * D], g_qkv_l[SQ * 3 * D];
__device__ __nv_bfloat16 g_ctx_h[SQ * D], g_ctx_l[SQ * D];
__device__ __nv_bfloat16 g_mha_h[SQ * D], g_mha_l[SQ * D];
__device__ float         g_p1[SQ * D];
__device__ float         g_n2[SQ * D];
__device__ __nv_bfloat16 g_n2_h[SQ * D],  g_n2_l[SQ * D];
__device__ __nv_bfloat16 g_ff1_h[SQ * DFF], g_ff1_l[SQ * DFF];
__device__ float         g_attn_scratch[(size_t)NH * SQ * SQ];
__device__ __nv_bfloat16 g_attn_h[(size_t)NH * SQ * SQ];
__device__ __nv_bfloat16 g_attn_l[(size_t)NH * SQ * SQ];
// transposed/split weights [N, K]
__device__ __nv_bfloat16 g_wint_h[D * D],      g_wint_l[D * D];
__device__ __nv_bfloat16 g_wqkvt_h[3 * D * D], g_wqkvt_l[3 * D * D];
__device__ __nv_bfloat16 g_wot_h[D * D],       g_wot_l[D * D];
__device__ __nv_bfloat16 g_w2t_h[D * D],       g_w2t_l[D * D];
__device__ __nv_bfloat16 g_wf1t_h[DFF * D],    g_wf1t_l[DFF * D];
__device__ __nv_bfloat16 g_wf2t_h[D * DFF],    g_wf2t_l[D * DFF];
__device__ float         g_bqkv[3 * D];

// ================= batched weight prep ======================================
__device__ __forceinline__ void wprep_tile(
    const float* __restrict__ W, __nv_bfloat16* __restrict__ Th,
    __nv_bfloat16* __restrict__ Tl, int K, int N, int rowoff, int n0, int k0)
{
    __shared__ float t[32][33];
    const int tx = threadIdx.x, ty = threadIdx.y;
    for (int i = ty; i < 32; i += 8)
        t[i][tx] = W[(size_t)(k0 + i) * N + n0 + tx];
    __syncthreads();
    for (int i = ty; i < 32; i += 8) {
        float v = t[tx][i];
        __nv_bfloat16 h = __float2bfloat16_rn(v);
        size_t o = (size_t)(rowoff + n0 + i) * K + k0 + tx;
        Th[o] = h;
        Tl[o] = __float2bfloat16_rn(v - __bfloat162float(h));
    }
}

__global__ __launch_bounds__(256) void wprep_dd(
    const float* __restrict__ W_in, const float* __restrict__ Wq,
    const float* __restrict__ Wk,   const float* __restrict__ Wv,
    const float* __restrict__ Wo,   const float* __restrict__ W2,
    const float* __restrict__ bq,   const float* __restrict__ bk,
    const float* __restrict__ bv,
    __nv_bfloat16* winth, __nv_bfloat16* wintl,
    __nv_bfloat16* wqkvth, __nv_bfloat16* wqkvtl,
    __nv_bfloat16* woth, __nv_bfloat16* wotl,
    __nv_bfloat16* w2th, __nv_bfloat16* w2tl, float* bqkv)
{
    const int z = blockIdx.z;
    const float* W; __nv_bfloat16 *Th, *Tl; int rowoff = 0;
    switch (z) {
        case 0:  W = W_in; Th = winth;  Tl = wintl;  break;
        case 1:  W = Wq;   Th = wqkvth; Tl = wqkvtl; rowoff = 0;     break;
        case 2:  W = Wk;   Th = wqkvth; Tl = wqkvtl; rowoff = D;     break;
        case 3:  W = Wv;   Th = wqkvth; Tl = wqkvtl; rowoff = 2 * D; break;
        case 4:  W = Wo;   Th = woth;   Tl = wotl;   break;
        default: W = W2;   Th = w2th;   Tl = w2tl;   break;
    }
    wprep_tile(W, Th, Tl, D, D, rowoff, blockIdx.x * 32, blockIdx.y * 32);
    if (z >= 1 && z <= 3 && blockIdx.x == 0 && blockIdx.y == 0) {
        const float* b = (z == 1) ? bq : (z == 2) ? bk : bv;
        for (int j = threadIdx.y * 32 + threadIdx.x; j < D; j += 256)
            bqkv[(z - 1) * D + j] = b[j];
    }
}

__global__ __launch_bounds__(256) void wprep_ff(
    const float* __restrict__ Wf1, const float* __restrict__ Wf2,
    __nv_bfloat16* f1h, __nv_bfloat16* f1l,
    __nv_bfloat16* f2h, __nv_bfloat16* f2l)
{
    const int z = blockIdx.z;
    if (z == 0)
        wprep_tile(Wf1, f1h, f1l, D, DFF, 0, blockIdx.x * 32, blockIdx.y * 32);
    else
        wprep_tile(Wf2, f2h, f2l, DFF, D, 0, blockIdx.y * 32, blockIdx.x * 32);
}

// ================= LayerNorm (warp-shuffle reductions) ======================
template<int WF32, int WSPLIT>
__global__ __launch_bounds__(256) void ln_kernel(
    const float* __restrict__ x, const float* __restrict__ g,
    const float* __restrict__ b, float* __restrict__ outf,
    __nv_bfloat16* __restrict__ oh, __nv_bfloat16* __restrict__ ol)
{
    __shared__ float red[8];
    __shared__ float bc[2];
    const int row = blockIdx.x;
    const int tid = threadIdx.x;
    const int lane = tid & 31, warp = tid >> 5;
    float4 v = *(const float4*)(x + (size_t)row * D + tid * 4);

    float s = wred_sum(v.x + v.y + v.z + v.w);
    if (lane == 0) red[warp] = s;
    __syncthreads();
    if (warp == 0) {
        float t = red[lane & 7];
        t += __shfl_xor_sync(0xffffffffu, t, 1);
        t += __shfl_xor_sync(0xffffffffu, t, 2);
        t += __shfl_xor_sync(0xffffffffu, t, 4);
        if (lane == 0) bc[0] = t;
    }
    __syncthreads();
    const float mean = bc[0] * (1.0f / D);
    const float dx = v.x - mean, dy = v.y - mean, dz = v.z - mean, dw = v.w - mean;

    float s2 = wred_sum(dx * dx + dy * dy + dz * dz + dw * dw);
    if (lane == 0) red[warp] = s2;
    __syncthreads();
    if (warp == 0) {
        float t = red[lane & 7];
        t += __shfl_xor_sync(0xffffffffu, t, 1);
        t += __shfl_xor_sync(0xffffffffu, t, 2);
        t += __shfl_xor_sync(0xffffffffu, t, 4);
        if (lane == 0) bc[1] = t;
    }
    __syncthreads();
    const float inv = 1.0f / (sqrtf(bc[1] * (1.0f / D)) + 1e-6f);

    float4 gg = *(const float4*)(g + tid * 4);
    float4 bb = *(const float4*)(b + tid * 4);
    float o0 = gg.x * dx * inv + bb.x;
    float o1 = gg.y * dy * inv + bb.y;
    float o2 = gg.z * dz * inv + bb.z;
    float o3 = gg.w * dw * inv + bb.w;
    const size_t base = (size_t)row * D + tid * 4;
    if (WF32) {
        float4 o4 = {o0, o1, o2, o3};
        *(float4*)(outf + base) = o4;
    }
    if (WSPLIT) {
        float vv[4] = {o0, o1, o2, o3};
        __nv_bfloat16 hs[4], ls[4];
#pragma unroll
        for (int i = 0; i < 4; i++) {
            hs[i] = __float2bfloat16_rn(vv[i]);
            ls[i] = __float2bfloat16_rn(vv[i] - __bfloat162float(hs[i]));
        }
        *(uint2*)(oh + base) = *(uint2*)hs;
        *(uint2*)(ol + base) = *(uint2*)ls;
    }
}

// ================= shared GEMM plumbing ======================================
__device__ __forceinline__ uint32_t swz(int row, int kb) {
    return (uint32_t)(row * 64 + ((kb ^ ((row >> 1) & 3)) << 4));
}

template<int ROWS>
__device__ __forceinline__ void load_tileT(
    const __nv_bfloat16* __restrict__ g, int ld, int row0, int k0, uint32_t sbase, int tid)
{
#pragma unroll
    for (int it = 0; it < ROWS / 64; it++) {
        int c = tid + (it << 8);
        int row = c >> 2, kb = c & 3;
        cpa16(sbase + swz(row, kb), g + (size_t)(row0 + row) * ld + k0 + kb * 8);
    }
}

// ================= mma.sync GEMM (2-stage, occ 2): C = A[M,K] @ T[N,K]^T =====
// BN: CTA tile N (128 or 64); M tile always 128.
template<int BN, int WF32, int WSPLIT, int RELU, int RESID>
__global__ __launch_bounds__(256, 2) void mma_gemm(
    const __nv_bfloat16* __restrict__ Ah, const __nv_bfloat16* __restrict__ Al,
    const __nv_bfloat16* __restrict__ Bh, const __nv_bfloat16* __restrict__ Bl,
    const float* __restrict__ bias, const float* __restrict__ res,
    float* __restrict__ Cf, __nv_bfloat16* __restrict__ Chi, __nv_bfloat16* __restrict__ Clo,
    int N, int K)
{
    constexpr int MT   = (BN == 128) ? 4 : 2;   // 16-row groups per warp
    constexpr int BB   = BN * 64;               // one B (h or l) tile bytes
    constexpr int SA_H = 0, SA_L = 8192, SB_H = 16384;
    constexpr int SB_L = 16384 + BB;
    constexpr int SSZ  = 16384 + 2 * BB;

    extern __shared__ char smem[];
    const uint32_t sb = smem_u32(smem);
    const int tid = threadIdx.x, wid = tid >> 5, lane = tid & 31;
    const int warp_m = (BN == 128) ? (wid & 1) : (wid & 3);
    const int warp_n = (BN == 128) ? (wid >> 1) : (wid >> 2);
    const int brow = blockIdx.y * 128, bcol = blockIdx.x * BN;

    float acc[MT][4][4];
#pragma unroll
    for (int a = 0; a < MT; a++)
#pragma unroll
        for (int b = 0; b < 4; b++)
#pragma unroll
            for (int c = 0; c < 4; c++) acc[a][b][c] = 0.0f;

    const int nch = K >> 5;
    load_tileT<128>(Ah, K, brow, 0, sb + SA_H, tid);
    load_tileT<128>(Al, K, brow, 0, sb + SA_L, tid);
    load_tileT<BN>(Bh, K, bcol, 0, sb + SB_H, tid);
    load_tileT<BN>(Bl, K, bcol, 0, sb + SB_L, tid);
    CPA_COMMIT();

    const int tileA = lane >> 3;
    const int rinA  = (lane & 7) + ((tileA & 1) << 3);
    const int kbA   = tileA >> 1;
    const int i16   = lane & 15;
    const int rinB  = i16 & 7;
    const int kbB   = i16 >> 3;

    for (int i = 0; i < nch; i++) {
        if (i + 1 < nch) {
            const uint32_t st = sb + ((i + 1) & 1) * SSZ;
            const int k0 = (i + 1) << 5;
            load_tileT<128>(Ah, K, brow, k0, st + SA_H, tid);
            load_tileT<128>(Al, K, brow, k0, st + SA_L, tid);
            load_tileT<BN>(Bh, K, bcol, k0, st + SB_H, tid);
            load_tileT<BN>(Bl, K, bcol, k0, st + SB_L, tid);
            CPA_COMMIT();
            asm volatile("cp.async.wait_group 1;" ::: "memory");
        } else {
            asm volatile("cp.async.wait_group 0;" ::: "memory");
        }
        __syncthreads();

        const uint32_t st = sb + (i & 1) * SSZ;
#pragma unroll
        for (int ks = 0; ks < 2; ks++) {
            uint32_t bh[4][2], bl[4][2];
#pragma unroll
            for (int nt = 0; nt < 4; nt++) {
                const int rowb = warp_n * 32 + nt * 8 + rinB;
                const uint32_t off = swz(rowb, (ks << 1) + kbB);
                ldm_x2(bh[nt][0], bh[nt][1], st + SB_H + off);
                ldm_x2(bl[nt][0], bl[nt][1], st + SB_L + off);
            }
#pragma unroll
            for (int mt = 0; mt < MT; mt++) {
                const int rowa = warp_m * (MT * 16) + mt * 16 + rinA;
                const uint32_t off = swz(rowa, (ks << 1) + kbA);
                uint32_t a0, a1, a2, a3, l0, l1, l2, l3;
                ldm_x4(a0, a1, a2, a3, st + SA_H + off);
                ldm_x4(l0, l1, l2, l3, st + SA_L + off);
#pragma unroll
                for (int nt = 0; nt < 4; nt++) {
                    mma_bf16(acc[mt][nt], a0, a1, a2, a3, bh[nt][0], bh[nt][1]);
                    mma_bf16(acc[mt][nt], a0, a1, a2, a3, bl[nt][0], bl[nt][1]);
                    mma_bf16(acc[mt][nt], l0, l1, l2, l3, bh[nt][0], bh[nt][1]);
                }
            }
        }
        __syncthreads();
    }

    const int g4 = lane >> 2, t4 = lane & 3;
#pragma unroll
    for (int mt = 0; mt < MT; mt++) {
#pragma unroll
        for (int half = 0; half < 2; half++) {
            const int row = brow + warp_m * (MT * 16) + mt * 16 + g4 + half * 8;
#pragma unroll
            for (int nt = 0; nt < 4; nt++) {
                const int col = bcol + warp_n * 32 + nt * 8 + t4 * 2;
                float v0 = acc[mt][nt][half * 2 + 0] + bias[col];
                float v1 = acc[mt][nt][half * 2 + 1] + bias[col + 1];
                if (RELU) { v0 = fmaxf(v0, 0.0f); v1 = fmaxf(v1, 0.0f); }
                const size_t o = (size_t)row * N + col;
                if (RESID) { v0 += res[o]; v1 += res[o + 1]; }
                if (WF32) {
                    float2 f2 = {v0, v1};
                    *(float2*)(Cf + o) = f2;
                }
                if (WSPLIT) {
                    __nv_bfloat16 h0 = __float2bfloat16_rn(v0);
                    __nv_bfloat16 h1 = __float2bfloat16_rn(v1);
                    __nv_bfloat16 q0 = __float2bfloat16_rn(v0 - __bfloat162float(h0));
                    __nv_bfloat16 q1 = __float2bfloat16_rn(v1 - __bfloat162float(h1));
                    __nv_bfloat162 hp = {h0, h1}, lp = {q0, q1};
                    *(__nv_bfloat162*)(Chi + o) = hp;
                    *(__nv_bfloat162*)(Clo + o) = lp;
                }
            }
        }
    }
}

#define GSTG_128 32768
#define GSMEM_128 (2 * GSTG_128)
#define GSTG_64 24576
#define GSMEM_64 (2 * GSTG_64)

// ================= score mma: S = (Q K^T)/8, causal ==========================
#define STG_A_H 0
#define STG_A_L 8192
#define STG_B_H 16384
#define STG_B_L 24576
#define STG_SZ  32768
#define SCORE_SMEM (2 * STG_SZ)

__global__ __launch_bounds__(256, 2) void score_mma(
    const __nv_bfloat16* __restrict__ qh, const __nv_bfloat16* __restrict__ ql,
    const __nv_bfloat16* __restrict__ kh, const __nv_bfloat16* __restrict__ kl,
    float* __restrict__ attn)
{
    const int brow = blockIdx.y * 128, bcol = blockIdx.x * 128;
    if (bcol >= brow + 128) return;
    const int h = blockIdx.z;
    const __nv_bfloat16* Ah = qh + h * DK;
    const __nv_bfloat16* Al = ql + h * DK;
    const __nv_bfloat16* Bh = kh + h * DK;
    const __nv_bfloat16* Bl = kl + h * DK;

    extern __shared__ char smem[];
    const uint32_t sb = smem_u32(smem);
    const int tid = threadIdx.x, wid = tid >> 5, lane = tid & 31;
    const int warp_m = wid & 1, warp_n = wid >> 1;

    float acc[4][4][4];
#pragma unroll
    for (int a = 0; a < 4; a++)
#pragma unroll
        for (int b = 0; b < 4; b++)
#pragma unroll
            for (int c = 0; c < 4; c++) acc[a][b][c] = 0.0f;

    load_tileT<128>(Ah, 3 * D, brow, 0, sb + STG_A_H, tid);
    load_tileT<128>(Al, 3 * D, brow, 0, sb + STG_A_L, tid);
    load_tileT<128>(Bh, 3 * D, bcol, 0, sb + STG_B_H, tid);
    load_tileT<128>(Bl, 3 * D, bcol, 0, sb + STG_B_L, tid);
    CPA_COMMIT();

    const int tileA = lane >> 3;
    const int rinA  = (lane & 7) + ((tileA & 1) << 3);
    const int kbA   = tileA >> 1;
    const int i16   = lane & 15;
    const int rinB  = i16 & 7;
    const int kbB   = i16 >> 3;

    for (int i = 0; i < 2; i++) {
        if (i == 0) {
            const uint32_t st = sb + STG_SZ;
            load_tileT<128>(Ah, 3 * D, brow, 32, st + STG_A_H, tid);
            load_tileT<128>(Al, 3 * D, brow, 32, st + STG_A_L, tid);
            load_tileT<128>(Bh, 3 * D, bcol, 32, st + STG_B_H, tid);
            load_tileT<128>(Bl, 3 * D, bcol, 32, st + STG_B_L, tid);
            CPA_COMMIT();
            asm volatile("cp.async.wait_group 1;" ::: "memory");
        } else {
            asm volatile("cp.async.wait_group 0;" ::: "memory");
        }
        __syncthreads();

        const uint32_t st = sb + (i & 1) * STG_SZ;
#pragma unroll
        for (int ks = 0; ks < 2; ks++) {
            uint32_t bh[4][2], bl[4][2];
#pragma unroll
            for (int nt = 0; nt < 4; nt++) {
                const int rowb = warp_n * 32 + nt * 8 + rinB;
                const uint32_t off = swz(rowb, (ks << 1) + kbB);
                ldm_x2(bh[nt][0], bh[nt][1], st + STG_B_H + off);
                ldm_x2(bl[nt][0], bl[nt][1], st + STG_B_L + off);
            }
#pragma unroll
            for (int mt = 0; mt < 4; mt++) {
                const int rowa = warp_m * 64 + mt * 16 + rinA;
                const uint32_t off = swz(rowa, (ks << 1) + kbA);
                uint32_t a0, a1, a2, a3, l0, l1, l2, l3;
                ldm_x4(a0, a1, a2, a3, st + STG_A_H + off);
                ldm_x4(l0, l1, l2, l3, st + STG_A_L + off);
#pragma unroll
                for (int nt = 0; nt < 4; nt++) {
                    mma_bf16(acc[mt][nt], a0, a1, a2, a3, bh[nt][0], bh[nt][1]);
                    mma_bf16(acc[mt][nt], a0, a1, a2, a3, bl[nt][0], bl[nt][1]);
                    mma_bf16(acc[mt][nt], l0, l1, l2, l3, bh[nt][0], bh[nt][1]);
                }
            }
        }
        __syncthreads();
    }

    const int g4 = lane >> 2, t4 = lane & 3;
#pragma unroll
    for (int mt = 0; mt < 4; mt++) {
#pragma unroll
        for (int half = 0; half < 2; half++) {
            const int row = brow + warp_m * 64 + mt * 16 + g4 + half * 8;
            float* arow = attn + ((size_t)h * SQ + row) * SQ;
#pragma unroll
            for (int nt = 0; nt < 4; nt++) {
                const int col = bcol + warp_n * 32 + nt * 8 + t4 * 2;
                if (col <= row)     arow[col]     = acc[mt][nt][half * 2 + 0] * 0.125f;
                if (col + 1 <= row) arow[col + 1] = acc[mt][nt][half * 2 + 1] * 0.125f;
            }
        }
    }
}

// ================= softmax (warp-shuffle): fp32 out + bf16 hi/lo =============
__global__ __launch_bounds__(256) void softmax_kernel(
    float* __restrict__ attn,
    __nv_bfloat16* __restrict__ ah, __nv_bfloat16* __restrict__ al)
{
    __shared__ float p[SQ];
    __shared__ float red[8];
    __shared__ float bc[2];
    const int i   = blockIdx.x;
    const int h   = blockIdx.y;
    const int tid = threadIdx.x;
    const int lane = tid & 31, warp = tid >> 5;
    const size_t rb = ((size_t)h * SQ + i) * SQ;
    float* row = attn + rb;

    float m = -INFINITY;
    for (int j = tid; j <= i; j += 256) { float s = row[j]; p[j] = s; m = fmaxf(m, s); }
    m = wred_max(m);
    if (lane == 0) red[warp] = m;
    __syncthreads();
    if (warp == 0) {
        float t = red[lane & 7];
        t = fmaxf(t, __shfl_xor_sync(0xffffffffu, t, 1));
        t = fmaxf(t, __shfl_xor_sync(0xffffffffu, t, 2));
        t = fmaxf(t, __shfl_xor_sync(0xffffffffu, t, 4));
        if (lane == 0) bc[0] = t;
    }
    __syncthreads();
    const float mx = bc[0];

    float sum = 0.0f;
    for (int j = tid; j <= i; j += 256) { float e = __expf(p[j] - mx); p[j] = e; sum += e; }
    sum = wred_sum(sum);
    __syncthreads();
    if (lane == 0) red[warp] = sum;
    __syncthreads();
    if (warp == 0) {
        float t = red[lane & 7];
        t += __shfl_xor_sync(0xffffffffu, t, 1);
        t += __shfl_xor_sync(0xffffffffu, t, 2);
        t += __shfl_xor_sync(0xffffffffu, t, 4);
        if (lane == 0) bc[1] = t;
    }
    __syncthreads();
    const float inv = 1.0f / bc[1];

    const int lim = ((i >> 7) + 1) << 7;
    for (int j = tid; j <= i; j += 256) {
        float w = p[j] * inv;
        row[j] = w;
        __nv_bfloat16 hh = __float2bfloat16_rn(w);
        ah[rb + j] = hh;
        al[rb + j] = __float2bfloat16_rn(w - __bfloat162float(hh));
    }
    for (int j = i + 1 + tid; j < SQ; j += 256) row[j] = 0.0f;
    const __nv_bfloat16 z = __float2bfloat16_rn(0.0f);
    for (int j = i + 1 + tid; j < lim; j += 256) { ah[rb + j] = z; al[rb + j] = z; }
}

// ================= AV mma (2-stage, occ 2): ctx = P @ V ======================
#define AV_A_H 0
#define AV_A_L 8192
#define AV_B_H 16384
#define AV_B_L 20480
#define AV_STG 24576
#define AV_SMEM (2 * AV_STG)

__global__ __launch_bounds__(256, 2) void av_mma(
    const __nv_bfloat16* __restrict__ ah, const __nv_bfloat16* __restrict__ al,
    const __nv_bfloat16* __restrict__ vh, const __nv_bfloat16* __restrict__ vl,
    __nv_bfloat16* __restrict__ ch, __nv_bfloat16* __restrict__ cl)
{
    const int brow = blockIdx.x * 128;
    const int h    = blockIdx.y;
    const __nv_bfloat16* Ah = ah + (size_t)h * SQ * SQ;
    const __nv_bfloat16* Al = al + (size_t)h * SQ * SQ;
    const __nv_bfloat16* Vh = vh + 2 * D + h * DK;
    const __nv_bfloat16* Vl = vl + 2 * D + h * DK;

    extern __shared__ char smem[];
    const uint32_t sb = smem_u32(smem);
    const int tid = threadIdx.x, wid = tid >> 5, lane = tid & 31;
    const int warp_m = wid & 3;
    const int warp_n = wid >> 2;

    float acc[2][4][4];
#pragma unroll
    for (int a = 0; a < 2; a++)
#pragma unroll
        for (int b = 0; b < 4; b++)
#pragma unroll
            for (int c = 0; c < 4; c++) acc[a][b][c] = 0.0f;

    auto load_b = [&](const __nv_bfloat16* V, int k0, uint32_t sbase) {
        int r = tid >> 3, g = tid & 7;
        cpa16(sbase + (uint32_t)(r * 128 + ((g ^ (r & 7)) << 4)),
              V + (size_t)(k0 + r) * (3 * D) + g * 8);
    };
    auto load_stage = [&](int ci, uint32_t st) {
        const int k0 = ci << 5;
        load_tileT<128>(Ah, SQ, brow, k0, st + AV_A_H, tid);
        load_tileT<128>(Al, SQ, brow, k0, st + AV_A_L, tid);
        load_b(Vh, k0, st + AV_B_H);
        load_b(Vl, k0, st + AV_B_L);
        CPA_COMMIT();
    };

    const int nch = (brow >> 5) + 4;
    load_stage(0, sb);

    const int tileA = lane >> 3;
    const int rinA  = (lane & 7) + ((tileA & 1) << 3);
    const int kbA   = tileA >> 1;
    const int i16   = lane & 15;

    for (int i = 0; i < nch; i++) {
        if (i + 1 < nch) {
            load_stage(i + 1, sb + ((i + 1) & 1) * AV_STG);
            asm volatile("cp.async.wait_group 1;" ::: "memory");
        } else {
            asm volatile("cp.async.wait_group 0;" ::: "memory");
        }
        __syncthreads();

        const uint32_t st = sb + (i & 1) * AV_STG;
#pragma unroll
        for (int ks = 0; ks < 2; ks++) {
            uint32_t bh[4][2], bl[4][2];
#pragma unroll
            for (int nt = 0; nt < 4; nt++) {
                const int krow = ks * 16 + i16;
                const int gB = warp_n * 4 + nt;
                const uint32_t off = (uint32_t)(krow * 128 + ((gB ^ (krow & 7)) << 4));
                ldm_x2t(bh[nt][0], bh[nt][1], st + AV_B_H + off);
                ldm_x2t(bl[nt][0], bl[nt][1], st + AV_B_L + off);
            }
#pragma unroll
            for (int mt = 0; mt < 2; mt++) {
                const int rowa = warp_m * 32 + mt * 16 + rinA;
                const uint32_t off = swz(rowa, (ks << 1) + kbA);
                uint32_t a0, a1, a2, a3, l0, l1, l2, l3;
                ldm_x4(a0, a1, a2, a3, st + AV_A_H + off);
                ldm_x4(l0, l1, l2, l3, st + AV_A_L + off);
#pragma unroll
                for (int nt = 0; nt < 4; nt++) {
                    mma_bf16(acc[mt][nt], a0, a1, a2, a3, bh[nt][0], bh[nt][1]);
                    mma_bf16(acc[mt][nt], a0, a1, a2, a3, bl[nt][0], bl[nt][1]);
                    mma_bf16(acc[mt][nt], l0, l1, l2, l3, bh[nt][0], bh[nt][1]);
                }
            }
        }
        __syncthreads();
    }

    const int g4 = lane >> 2, t4 = lane & 3;
#pragma unroll
    for (int mt = 0; mt < 2; mt++) {
#pragma unroll
        for (int half = 0; half < 2; half++) {
            const int row = brow + warp_m * 32 + mt * 16 + g4 + half * 8;
#pragma unroll
            for (int nt = 0; nt < 4; nt++) {
                const int col = h * DK + warp_n * 32 + nt * 8 + t4 * 2;
                float v0 = acc[mt][nt][half * 2 + 0];
                float v1 = acc[mt][nt][half * 2 + 1];
                const size_t o = (size_t)row * D + col;
                __nv_bfloat16 h0 = __float2bfloat16_rn(v0);
                __nv_bfloat16 h1 = __float2bfloat16_rn(v1);
                __nv_bfloat16 q0 = __float2bfloat16_rn(v0 - __bfloat162float(h0));
                __nv_bfloat16 q1 = __float2bfloat16_rn(v1 - __bfloat162float(h1));
                __nv_bfloat162 hp = {h0, h1}, lp = {q0, q1};
                *(__nv_bfloat162*)(ch + o) = hp;
                *(__nv_bfloat162*)(cl + o) = lp;
            }
        }
    }
}

// ================= host driver =================
struct Scratch {
    __nv_bfloat16 *nxh, *nxl, *hh, *hl, *qkvh, *qkvl, *ctxh, *ctxl, *mhah, *mhal, *n2h, *n2l, *ff1h, *ff1l;
    __nv_bfloat16 *attnh, *attnl;
    __nv_bfloat16 *winth, *wintl, *wqkvth, *wqkvtl, *woth, *wotl, *w2th, *w2tl, *wf1th, *wf1tl, *wf2th, *wf2tl;
    float *p1, *n2, *attn, *bqkv;
};

static Scratch get_scratch() {
    static Scratch s = [] {
        Scratch t;
        void* p;
        cudaGetSymbolAddress(&p, g_nx_h);   t.nxh = (__nv_bfloat16*)p;
        cudaGetSymbolAddress(&p, g_nx_l);   t.nxl = (__nv_bfloat16*)p;
        cudaGetSymbolAddress(&p, g_h_h);    t.hh  = (__nv_bfloat16*)p;
        cudaGetSymbolAddress(&p, g_h_l);    t.hl  = (__nv_bfloat16*)p;
        cudaGetSymbolAddress(&p, g_qkv_h);  t.qkvh = (__nv_bfloat16*)p;
        cudaGetSymbolAddress(&p, g_qkv_l);  t.qkvl = (__nv_bfloat16*)p;
        cudaGetSymbolAddress(&p, g_ctx_h);  t.ctxh = (__nv_bfloat16*)p;
        cudaGetSymbolAddress(&p, g_ctx_l);  t.ctxl = (__nv_bfloat16*)p;
        cudaGetSymbolAddress(&p, g_mha_h);  t.mhah = (__nv_bfloat16*)p;
        cudaGetSymbolAddress(&p, g_mha_l);  t.mhal = (__nv_bfloat16*)p;
        cudaGetSymbolAddress(&p, g_n2_h);   t.n2h = (__nv_bfloat16*)p;
        cudaGetSymbolAddress(&p, g_n2_l);   t.n2l = (__nv_bfloat16*)p;
        cudaGetSymbolAddress(&p, g_ff1_h);  t.ff1h = (__nv_bfloat16*)p;
        cudaGetSymbolAddress(&p, g_ff1_l);  t.ff1l = (__nv_bfloat16*)p;
        cudaGetSymbolAddress(&p, g_attn_h); t.attnh = (__nv_bfloat16*)p;
        cudaGetSymbolAddress(&p, g_attn_l); t.attnl = (__nv_bfloat16*)p;
        cudaGetSymbolAddress(&p, g_wint_h); t.winth = (__nv_bfloat16*)p;
        cudaGetSymbolAddress(&p, g_wint_l); t.wintl = (__nv_bfloat16*)p;
        cudaGetSymbolAddress(&p, g_wqkvt_h); t.wqkvth = (__nv_bfloat16*)p;
        cudaGetSymbolAddress(&p, g_wqkvt_l); t.wqkvtl = (__nv_bfloat16*)p;
        cudaGetSymbolAddress(&p, g_wot_h);  t.woth = (__nv_bfloat16*)p;
        cudaGetSymbolAddress(&p, g_wot_l);  t.wotl = (__nv_bfloat16*)p;
        cudaGetSymbolAddress(&p, g_w2t_h);  t.w2th = (__nv_bfloat16*)p;
        cudaGetSymbolAddress(&p, g_w2t_l);  t.w2tl = (__nv_bfloat16*)p;
        cudaGetSymbolAddress(&p, g_wf1t_h); t.wf1th = (__nv_bfloat16*)p;
        cudaGetSymbolAddress(&p, g_wf1t_l); t.wf1tl = (__nv_bfloat16*)p;
        cudaGetSymbolAddress(&p, g_wf2t_h); t.wf2th = (__nv_bfloat16*)p;
        cudaGetSymbolAddress(&p, g_wf2t_l); t.wf2tl = (__nv_bfloat16*)p;
        cudaGetSymbolAddress(&p, g_p1);     t.p1  = (float*)p;
        cudaGetSymbolAddress(&p, g_n2);     t.n2  = (float*)p;
        cudaGetSymbolAddress(&p, g_attn_scratch); t.attn = (float*)p;
        cudaGetSymbolAddress(&p, g_bqkv);   t.bqkv = (float*)p;
        cudaFuncSetAttribute((const void*)mma_gemm<64,0,1,0,0>,  cudaFuncAttributeMaxDynamicSharedMemorySize, GSMEM_64);
        cudaFuncSetAttribute((const void*)mma_gemm<64,1,0,0,1>,  cudaFuncAttributeMaxDynamicSharedMemorySize, GSMEM_64);
        cudaFuncSetAttribute((const void*)mma_gemm<128,0,1,0,0>, cudaFuncAttributeMaxDynamicSharedMemorySize, GSMEM_128);
        cudaFuncSetAttribute((const void*)mma_gemm<128,0,1,1,0>, cudaFuncAttributeMaxDynamicSharedMemorySize, GSMEM_128);
        cudaFuncSetAttribute((const void*)score_mma, cudaFuncAttributeMaxDynamicSharedMemorySize, SCORE_SMEM);
        cudaFuncSetAttribute((const void*)av_mma,    cudaFuncAttributeMaxDynamicSharedMemorySize, AV_SMEM);
        return t;
    }();
    return s;
}

extern "C" void kernel_launch(void* const* d_in, const int* in_sizes, int n_in,
                              void* d_out, int out_size)
{
    const float* x     = (const float*)d_in[0];
    const float* g1    = (const float*)d_in[1];
    const float* beta1 = (const float*)d_in[2];
    const float* W_in  = (const float*)d_in[3];
    const float* b_in  = (const float*)d_in[4];
    const float* Wq    = (const float*)d_in[5];
    const float* bq    = (const float*)d_in[6];
    const float* Wk    = (const float*)d_in[7];
    const float* bk    = (const float*)d_in[8];
    const float* Wv    = (const float*)d_in[9];
    const float* bv    = (const float*)d_in[10];
    const float* Wo    = (const float*)d_in[11];
    const float* bo    = (const float*)d_in[12];
    const float* W2    = (const float*)d_in[13];
    const float* b2    = (const float*)d_in[14];
    const float* g2    = (const float*)d_in[15];
    const float* beta2 = (const float*)d_in[16];
    const float* Wf1   = (const float*)d_in[17];
    const float* bf1   = (const float*)d_in[18];
    const float* Wf2   = (const float*)d_in[19];
    const float* bf2   = (const float*)d_in[20];

    Scratch s = get_scratch();

    float* out  = (float*)d_out;
    const long long full = (long long)SQ * D + (long long)NH * SQ * SQ;
    float* attn = ((long long)out_size >= full) ? (out + (size_t)SQ * D) : s.attn;

    dim3 blk(256);
    dim3 wblk(32, 8);

    // #1/#2: batched weight prep
    wprep_dd<<<dim3(32, 32, 6), wblk>>>(
        W_in, Wq, Wk, Wv, Wo, W2, bq, bk, bv,
        s.winth, s.wintl, s.wqkvth, s.wqkvtl, s.woth, s.wotl, s.w2th, s.w2tl, s.bqkv);
    wprep_ff<<<dim3(128, 32, 2), wblk>>>(Wf1, Wf2, s.wf1th, s.wf1tl, s.wf2th, s.wf2tl);

    // #3: LN1 -> split
    ln_kernel<0,1><<<SQ, blk>>>(x, g1, beta1, nullptr, s.nxh, s.nxl);
    // #4: h = nx @ W_in + b_in (BN=64, grid 256)
    mma_gemm<64,0,1,0,0><<<dim3(D/64, SQ/128), 256, GSMEM_64>>>(
        s.nxh, s.nxl, s.winth, s.wintl, b_in, nullptr, nullptr, s.hh, s.hl, D, D);
    // #5: qkv (BN=128, grid 384)
    mma_gemm<128,0,1,0,0><<<dim3(3*D/128, SQ/128), 256, GSMEM_128>>>(
        s.hh, s.hl, s.wqkvth, s.wqkvtl, s.bqkv, nullptr, nullptr, s.qkvh, s.qkvl, 3*D, D);
    // #6: scores  [ncu -s 5 captures this]
    score_mma<<<dim3(SQ/128, SQ/128, NH), 256, SCORE_SMEM>>>(
        s.qkvh, s.qkvl, s.qkvh + D, s.qkvl + D, attn);
    // #7: softmax
    softmax_kernel<<<dim3(SQ, NH), blk>>>(attn, s.attnh, s.attnl);
    // #8: AV
    av_mma<<<dim3(SQ/128, NH), 256, AV_SMEM>>>(
        s.attnh, s.attnl, s.qkvh, s.qkvl, s.ctxh, s.ctxl);
    // #9: mha = ctx @ Wo + bo (BN=64)
    mma_gemm<64,0,1,0,0><<<dim3(D/64, SQ/128), 256, GSMEM_64>>>(
        s.ctxh, s.ctxl, s.woth, s.wotl, bo, nullptr, nullptr, s.mhah, s.mhal, D, D);
    // #10: p1 = x + mha @ W2 + b2 (BN=64)
    mma_gemm<64,1,0,0,1><<<dim3(D/64, SQ/128), 256, GSMEM_64>>>(
        s.mhah, s.mhal, s.w2th, s.w2tl, b2, x, s.p1, nullptr, nullptr, D, D);
    // #11: LN2
    ln_kernel<1,1><<<SQ, blk>>>(s.p1, g2, beta2, s.n2, s.n2h, s.n2l);
    // #12: ff1 = relu(n2 @ Wf1 + bf1) (BN=128, grid 512)
    mma_gemm<128,0,1,1,0><<<dim3(DFF/128, SQ/128), 256, GSMEM_128>>>(
        s.n2h, s.n2l, s.wf1th, s.wf1tl, bf1, nullptr, nullptr, s.ff1h, s.ff1l, DFF, D);
    // #13: out = n2 + ff1 @ Wf2 + bf2 (BN=64, K=4096)
    mma_gemm<64,1,0,0,1><<<dim3(D/64, SQ/128), 256, GSMEM_64>>>(
        s.ff1h, s.ff1l, s.wf2th, s.wf2tl, bf2, s.n2, out, nullptr, nullptr, D, DFF);
}